// round 1
// baseline (speedup 1.0000x reference)
#include <cuda_runtime.h>
#include <math.h>

#define N_NODES 4096
#define D_MODEL 512
#define N_HEADS 8
#define D_HEAD  64
#define D_FF    2048
#define N_EDGES 65536

// ---------------- scratch (static device globals; no allocations) ----------------
__device__ float g_xt [N_NODES * D_MODEL];
__device__ float g_mp [N_NODES * D_MODEL];
__device__ float g_dinv[N_NODES];
__device__ float g_h  [N_NODES * D_MODEL];
__device__ float g_q  [N_NODES * D_MODEL];
__device__ float g_k  [N_NODES * D_MODEL];
__device__ float g_v  [N_NODES * D_MODEL];
__device__ float g_o  [N_NODES * D_MODEL];
__device__ float g_x1 [N_NODES * D_MODEL];
__device__ float g_h2 [N_NODES * D_MODEL];
__device__ float g_m1 [N_NODES * D_FF];
__device__ float g_tf [N_NODES * D_MODEL];
__device__ float g_cat[N_NODES * 2 * D_MODEL];

// ---------------- helpers ----------------
__device__ __forceinline__ float gelu_tanh(float x) {
    float x3 = x * x * x;
    float t  = tanhf(0.7978845608028654f * (x + 0.044715f * x3));
    return 0.5f * x * (1.0f + t);
}

// ---------------- SGEMM: C[M,N] = A[M,K] @ B[K,N] (+bias)(+gelu)(+res) ----------
// All dims are multiples of (128,128,16) for every call in this problem.
#define EPI_NONE      0
#define EPI_BIAS      1
#define EPI_BIAS_GELU 2
#define EPI_BIAS_RES  3

template<int EPI>
__global__ __launch_bounds__(256, 2)
void sgemm_k(const float* __restrict__ A, const float* __restrict__ B,
             float* __restrict__ C, const float* __restrict__ bias,
             const float* __restrict__ res, int M, int Nc, int K)
{
    __shared__ float As[16][128];
    __shared__ float Bs[16][128];

    const int bm  = blockIdx.y * 128;
    const int bn  = blockIdx.x * 128;
    const int tid = threadIdx.x;
    const int ty  = tid >> 4;      // 0..15
    const int tx  = tid & 15;      // 0..15

    const int ar = tid >> 2;            // 0..63
    const int ac = (tid & 3) << 2;      // 0,4,8,12
    const int br = tid >> 5;            // 0..7
    const int bc = (tid & 31) << 2;     // 0..124

    float acc[8][8];
#pragma unroll
    for (int i = 0; i < 8; i++)
#pragma unroll
        for (int j = 0; j < 8; j++) acc[i][j] = 0.0f;

    for (int k0 = 0; k0 < K; k0 += 16) {
        float4 a0 = *(const float4*)&A[(size_t)(bm + ar)      * K + k0 + ac];
        float4 a1 = *(const float4*)&A[(size_t)(bm + ar + 64) * K + k0 + ac];
        As[ac + 0][ar]      = a0.x; As[ac + 1][ar]      = a0.y;
        As[ac + 2][ar]      = a0.z; As[ac + 3][ar]      = a0.w;
        As[ac + 0][ar + 64] = a1.x; As[ac + 1][ar + 64] = a1.y;
        As[ac + 2][ar + 64] = a1.z; As[ac + 3][ar + 64] = a1.w;

        float4 b0 = *(const float4*)&B[(size_t)(k0 + br)     * Nc + bn + bc];
        float4 b1 = *(const float4*)&B[(size_t)(k0 + br + 8) * Nc + bn + bc];
        *(float4*)&Bs[br][bc]     = b0;
        *(float4*)&Bs[br + 8][bc] = b1;
        __syncthreads();

#pragma unroll
        for (int kk = 0; kk < 16; kk++) {
            float af[8], bf[8];
            *(float4*)&af[0] = *(const float4*)&As[kk][ty * 8];
            *(float4*)&af[4] = *(const float4*)&As[kk][ty * 8 + 4];
            *(float4*)&bf[0] = *(const float4*)&Bs[kk][tx * 8];
            *(float4*)&bf[4] = *(const float4*)&Bs[kk][tx * 8 + 4];
#pragma unroll
            for (int i = 0; i < 8; i++)
#pragma unroll
                for (int j = 0; j < 8; j++)
                    acc[i][j] = fmaf(af[i], bf[j], acc[i][j]);
        }
        __syncthreads();
    }

#pragma unroll
    for (int i = 0; i < 8; i++) {
        int row = bm + ty * 8 + i;
#pragma unroll
        for (int j = 0; j < 8; j += 4) {
            int col = bn + tx * 8 + j;
            float4 v;
            v.x = acc[i][j + 0]; v.y = acc[i][j + 1];
            v.z = acc[i][j + 2]; v.w = acc[i][j + 3];
            if (EPI != EPI_NONE) {
                float4 bb = *(const float4*)&bias[col];
                v.x += bb.x; v.y += bb.y; v.z += bb.z; v.w += bb.w;
            }
            if (EPI == EPI_BIAS_GELU) {
                v.x = gelu_tanh(v.x); v.y = gelu_tanh(v.y);
                v.z = gelu_tanh(v.z); v.w = gelu_tanh(v.w);
            }
            if (EPI == EPI_BIAS_RES) {
                float4 rr = *(const float4*)&res[(size_t)row * Nc + col];
                v.x += rr.x; v.y += rr.y; v.z += rr.z; v.w += rr.w;
            }
            *(float4*)&C[(size_t)row * Nc + col] = v;
        }
    }
}

// ---------------- LayerNorm over last dim (512) ----------------
__global__ void ln_k(const float* __restrict__ x, const float* __restrict__ s,
                     const float* __restrict__ b, float* __restrict__ y)
{
    const int row = blockIdx.x;
    const int tid = threadIdx.x;   // 256
    const float* xr = x + (size_t)row * D_MODEL;

    float v0 = xr[tid];
    float v1 = xr[tid + 256];
    float sum = v0 + v1;
    float sq  = v0 * v0 + v1 * v1;

#pragma unroll
    for (int off = 16; off > 0; off >>= 1) {
        sum += __shfl_xor_sync(0xffffffffu, sum, off);
        sq  += __shfl_xor_sync(0xffffffffu, sq,  off);
    }
    __shared__ float rs[8], rq[8];
    __shared__ float s_mean, s_inv;
    if ((tid & 31) == 0) { rs[tid >> 5] = sum; rq[tid >> 5] = sq; }
    __syncthreads();
    if (tid == 0) {
        float ts = 0.f, tq = 0.f;
#pragma unroll
        for (int i = 0; i < 8; i++) { ts += rs[i]; tq += rq[i]; }
        float mean = ts * (1.0f / D_MODEL);
        float var  = tq * (1.0f / D_MODEL) - mean * mean;
        s_mean = mean;
        s_inv  = rsqrtf(var + 1e-5f);
    }
    __syncthreads();
    float mean = s_mean, inv = s_inv;
    float* yr = y + (size_t)row * D_MODEL;
    yr[tid]       = (v0 - mean) * inv * s[tid]       + b[tid];
    yr[tid + 256] = (v1 - mean) * inv * s[tid + 256] + b[tid + 256];
}

// ---------------- GCN kernels ----------------
__global__ void deg_init_k() {
    int i = blockIdx.x * blockDim.x + threadIdx.x;
    if (i < N_NODES) g_dinv[i] = 1.0f;   // self-loop weight
}
__global__ void deg_acc_k(const int* __restrict__ ei, const float* __restrict__ ew) {
    int e = blockIdx.x * blockDim.x + threadIdx.x;
    if (e < N_EDGES) atomicAdd(&g_dinv[ei[N_EDGES + e]], ew[e]);
}
__global__ void deg_fin_k() {
    int i = blockIdx.x * blockDim.x + threadIdx.x;
    if (i < N_NODES) g_dinv[i] = rsqrtf(g_dinv[i]);   // deg >= 1 > 0 always
}
// mp[n,:] = xt[n,:] * dinv[n]^2 + bg   (self-loop contribution)
__global__ void mp_init_k(const float* __restrict__ bg) {
    int idx = blockIdx.x * blockDim.x + threadIdx.x;   // over N*D/4
    int n  = idx >> 7;            // /(512/4)
    int d4 = (idx & 127) << 2;
    float di = g_dinv[n];
    float c  = di * di;
    float4 xv = *(const float4*)&g_xt[(size_t)n * D_MODEL + d4];
    float4 bb = *(const float4*)&bg[d4];
    float4 r;
    r.x = fmaf(xv.x, c, bb.x); r.y = fmaf(xv.y, c, bb.y);
    r.z = fmaf(xv.z, c, bb.z); r.w = fmaf(xv.w, c, bb.w);
    *(float4*)&g_mp[(size_t)n * D_MODEL + d4] = r;
}
// scatter-add: mp[dst] += xt[src] * dinv[src]*w*dinv[dst]
__global__ void scatter_k(const int* __restrict__ ei, const float* __restrict__ ew) {
    int idx = blockIdx.x * blockDim.x + threadIdx.x;   // over E * 128
    int e  = idx >> 7;
    int d4 = (idx & 127) << 2;
    int s  = ei[e];
    int t  = ei[N_EDGES + e];
    float coef = g_dinv[s] * ew[e] * g_dinv[t];
    float4 xv = *(const float4*)&g_xt[(size_t)s * D_MODEL + d4];
    float* dstp = &g_mp[(size_t)t * D_MODEL + d4];
    atomicAdd(dstp + 0, xv.x * coef);
    atomicAdd(dstp + 1, xv.y * coef);
    atomicAdd(dstp + 2, xv.z * coef);
    atomicAdd(dstp + 3, xv.w * coef);
}

// ---------------- Flash attention (fp32, BM=BN=64, DH=64, 8 heads) ----------------
#define FA_PITCH 68
#define FLASH_SMEM (4 * 64 * FA_PITCH * 4)

__global__ __launch_bounds__(128)
void flash_k(const float* __restrict__ Q, const float* __restrict__ K,
             const float* __restrict__ V, float* __restrict__ O)
{
    extern __shared__ float sm[];
    float* Qs = sm;                    // [64][68]
    float* Ks = Qs + 64 * FA_PITCH;
    float* Vs = Ks + 64 * FA_PITCH;
    float* Ps = Vs + 64 * FA_PITCH;

    const int h   = blockIdx.y;
    const int qb  = blockIdx.x * 64;
    const int tid = threadIdx.x;       // 128
    const int ty  = tid >> 4;          // 0..7  -> 8 query rows each
    const int tx  = tid & 15;          // 0..15 -> 4 cols each
    const float scale = 0.125f;        // 1/sqrt(64)

    // load Q tile [64 x 64]
    for (int i = tid; i < 1024; i += 128) {      // 1024 float4s
        int r = i >> 4, c = (i & 15) << 2;
        *(float4*)&Qs[r * FA_PITCH + c] =
            *(const float4*)&Q[(size_t)(qb + r) * D_MODEL + h * D_HEAD + c];
    }

    float m_i[8], l_i[8], acc_o[8][4];
#pragma unroll
    for (int i = 0; i < 8; i++) {
        m_i[i] = -1e30f; l_i[i] = 0.0f;
#pragma unroll
        for (int j = 0; j < 4; j++) acc_o[i][j] = 0.0f;
    }

    for (int kb = 0; kb < N_NODES; kb += 64) {
        for (int i = tid; i < 1024; i += 128) {
            int r = i >> 4, c = (i & 15) << 2;
            *(float4*)&Ks[r * FA_PITCH + c] =
                *(const float4*)&K[(size_t)(kb + r) * D_MODEL + h * D_HEAD + c];
            *(float4*)&Vs[r * FA_PITCH + c] =
                *(const float4*)&V[(size_t)(kb + r) * D_MODEL + h * D_HEAD + c];
        }
        __syncthreads();

        // S = Q K^T  (8 rows x 4 keys per thread)
        float s[8][4];
#pragma unroll
        for (int i = 0; i < 8; i++)
#pragma unroll
            for (int j = 0; j < 4; j++) s[i][j] = 0.0f;

#pragma unroll
        for (int kk = 0; kk < 64; kk += 4) {
            float4 kf[4];
#pragma unroll
            for (int j = 0; j < 4; j++)
                kf[j] = *(const float4*)&Ks[(tx * 4 + j) * FA_PITCH + kk];
#pragma unroll
            for (int i = 0; i < 8; i++) {
                float4 qf = *(const float4*)&Qs[(ty * 8 + i) * FA_PITCH + kk];
#pragma unroll
                for (int j = 0; j < 4; j++) {
                    s[i][j] = fmaf(qf.x, kf[j].x, s[i][j]);
                    s[i][j] = fmaf(qf.y, kf[j].y, s[i][j]);
                    s[i][j] = fmaf(qf.z, kf[j].z, s[i][j]);
                    s[i][j] = fmaf(qf.w, kf[j].w, s[i][j]);
                }
            }
        }

        // online softmax per row (reduce across 16 tx lanes, width-16 shfl)
#pragma unroll
        for (int i = 0; i < 8; i++) {
            float mt = -1e30f;
#pragma unroll
            for (int j = 0; j < 4; j++) {
                s[i][j] *= scale;
                mt = fmaxf(mt, s[i][j]);
            }
#pragma unroll
            for (int off = 1; off < 16; off <<= 1)
                mt = fmaxf(mt, __shfl_xor_sync(0xffffffffu, mt, off, 16));
            float mnew = fmaxf(m_i[i], mt);
            float corr = __expf(m_i[i] - mnew);
            l_i[i] *= corr;
#pragma unroll
            for (int j = 0; j < 4; j++) acc_o[i][j] *= corr;
            float rs = 0.0f;
#pragma unroll
            for (int j = 0; j < 4; j++) {
                float p = __expf(s[i][j] - mnew);
                s[i][j] = p;
                rs += p;
            }
#pragma unroll
            for (int off = 1; off < 16; off <<= 1)
                rs += __shfl_xor_sync(0xffffffffu, rs, off, 16);
            l_i[i] += rs;
            m_i[i]  = mnew;
        }

        // store P to smem
#pragma unroll
        for (int i = 0; i < 8; i++) {
            float4 pv; pv.x = s[i][0]; pv.y = s[i][1]; pv.z = s[i][2]; pv.w = s[i][3];
            *(float4*)&Ps[(ty * 8 + i) * FA_PITCH + tx * 4] = pv;
        }
        __syncthreads();

        // O += P V  (8 rows x 4 dims per thread)
#pragma unroll
        for (int kk = 0; kk < 64; kk += 4) {
            float4 vf[4];
#pragma unroll
            for (int t = 0; t < 4; t++)
                vf[t] = *(const float4*)&Vs[(kk + t) * FA_PITCH + tx * 4];
#pragma unroll
            for (int i = 0; i < 8; i++) {
                float4 pf = *(const float4*)&Ps[(ty * 8 + i) * FA_PITCH + kk];
                acc_o[i][0] = fmaf(pf.x, vf[0].x, acc_o[i][0]);
                acc_o[i][1] = fmaf(pf.x, vf[0].y, acc_o[i][1]);
                acc_o[i][2] = fmaf(pf.x, vf[0].z, acc_o[i][2]);
                acc_o[i][3] = fmaf(pf.x, vf[0].w, acc_o[i][3]);
                acc_o[i][0] = fmaf(pf.y, vf[1].x, acc_o[i][0]);
                acc_o[i][1] = fmaf(pf.y, vf[1].y, acc_o[i][1]);
                acc_o[i][2] = fmaf(pf.y, vf[1].z, acc_o[i][2]);
                acc_o[i][3] = fmaf(pf.y, vf[1].w, acc_o[i][3]);
                acc_o[i][0] = fmaf(pf.z, vf[2].x, acc_o[i][0]);
                acc_o[i][1] = fmaf(pf.z, vf[2].y, acc_o[i][1]);
                acc_o[i][2] = fmaf(pf.z, vf[2].z, acc_o[i][2]);
                acc_o[i][3] = fmaf(pf.z, vf[2].w, acc_o[i][3]);
                acc_o[i][0] = fmaf(pf.w, vf[3].x, acc_o[i][0]);
                acc_o[i][1] = fmaf(pf.w, vf[3].y, acc_o[i][1]);
                acc_o[i][2] = fmaf(pf.w, vf[3].z, acc_o[i][2]);
                acc_o[i][3] = fmaf(pf.w, vf[3].w, acc_o[i][3]);
            }
        }
        __syncthreads();
    }

    // write O
#pragma unroll
    for (int i = 0; i < 8; i++) {
        float linv = 1.0f / l_i[i];
        int row = qb + ty * 8 + i;
        float4 ov;
        ov.x = acc_o[i][0] * linv; ov.y = acc_o[i][1] * linv;
        ov.z = acc_o[i][2] * linv; ov.w = acc_o[i][3] * linv;
        *(float4*)&O[(size_t)row * D_MODEL + h * D_HEAD + tx * 4] = ov;
    }
}

// ---------------- concat [mp | tf] -> cat [N, 1024] ----------------
__global__ void concat_k() {
    int idx = blockIdx.x * blockDim.x + threadIdx.x;   // over N*D/4
    int n  = idx >> 7;
    int d4 = (idx & 127) << 2;
    float4 a = *(const float4*)&g_mp[(size_t)n * D_MODEL + d4];
    float4 b = *(const float4*)&g_tf[(size_t)n * D_MODEL + d4];
    *(float4*)&g_cat[(size_t)n * (2 * D_MODEL) + d4]            = a;
    *(float4*)&g_cat[(size_t)n * (2 * D_MODEL) + D_MODEL + d4]  = b;
}

// ---------------- launch ----------------
extern "C" void kernel_launch(void* const* d_in, const int* in_sizes, int n_in,
                              void* d_out, int out_size)
{
    (void)in_sizes; (void)n_in; (void)out_size;
    const float* x     = (const float*)d_in[0];
    const int*   ei    = (const int*)  d_in[1];
    const float* ew    = (const float*)d_in[2];
    const float* Wg    = (const float*)d_in[3];
    const float* bg    = (const float*)d_in[4];
    const float* ln1_s = (const float*)d_in[5];
    const float* ln1_b = (const float*)d_in[6];
    const float* Wq    = (const float*)d_in[7];
    const float* bq    = (const float*)d_in[8];
    const float* Wk    = (const float*)d_in[9];
    const float* bk    = (const float*)d_in[10];
    const float* Wv    = (const float*)d_in[11];
    const float* bv    = (const float*)d_in[12];
    const float* Wo    = (const float*)d_in[13];
    const float* bo    = (const float*)d_in[14];
    const float* ln2_s = (const float*)d_in[15];
    const float* ln2_b = (const float*)d_in[16];
    const float* W1    = (const float*)d_in[17];
    const float* b1    = (const float*)d_in[18];
    const float* W2    = (const float*)d_in[19];
    const float* b2    = (const float*)d_in[20];
    const float* Wa    = (const float*)d_in[21];
    const float* ba    = (const float*)d_in[22];
    float* out = (float*)d_out;

    float *xt, *h, *q, *k, *v, *o, *x1, *h2, *m1, *tf, *cat;
    cudaGetSymbolAddress((void**)&xt,  g_xt);
    cudaGetSymbolAddress((void**)&h,   g_h);
    cudaGetSymbolAddress((void**)&q,   g_q);
    cudaGetSymbolAddress((void**)&k,   g_k);
    cudaGetSymbolAddress((void**)&v,   g_v);
    cudaGetSymbolAddress((void**)&o,   g_o);
    cudaGetSymbolAddress((void**)&x1,  g_x1);
    cudaGetSymbolAddress((void**)&h2,  g_h2);
    cudaGetSymbolAddress((void**)&m1,  g_m1);
    cudaGetSymbolAddress((void**)&tf,  g_tf);
    cudaGetSymbolAddress((void**)&cat, g_cat);

    cudaFuncSetAttribute(flash_k, cudaFuncAttributeMaxDynamicSharedMemorySize, FLASH_SMEM);

    dim3 g512(D_MODEL / 128, N_NODES / 128);     // (4, 32)
    dim3 gff (D_FF   / 128, N_NODES / 128);      // (16, 32)

    // ---- GCN branch ----
    sgemm_k<EPI_NONE><<<g512, 256>>>(x, Wg, xt, nullptr, nullptr, N_NODES, D_MODEL, D_MODEL);
    deg_init_k<<<N_NODES / 256, 256>>>();
    deg_acc_k<<<N_EDGES / 256, 256>>>(ei, ew);
    deg_fin_k<<<N_NODES / 256, 256>>>();
    mp_init_k<<<(N_NODES * D_MODEL / 4) / 256, 256>>>(bg);
    scatter_k<<<(N_EDGES * (D_MODEL / 4)) / 256, 256>>>(ei, ew);

    // ---- Transformer branch ----
    ln_k<<<N_NODES, 256>>>(x, ln1_s, ln1_b, h);
    sgemm_k<EPI_BIAS><<<g512, 256>>>(h, Wq, q, bq, nullptr, N_NODES, D_MODEL, D_MODEL);
    sgemm_k<EPI_BIAS><<<g512, 256>>>(h, Wk, k, bk, nullptr, N_NODES, D_MODEL, D_MODEL);
    sgemm_k<EPI_BIAS><<<g512, 256>>>(h, Wv, v, bv, nullptr, N_NODES, D_MODEL, D_MODEL);
    flash_k<<<dim3(N_NODES / 64, N_HEADS), 128, FLASH_SMEM>>>(q, k, v, o);
    sgemm_k<EPI_BIAS_RES><<<g512, 256>>>(o, Wo, x1, bo, x, N_NODES, D_MODEL, D_MODEL);
    ln_k<<<N_NODES, 256>>>(x1, ln2_s, ln2_b, h2);
    sgemm_k<EPI_BIAS_GELU><<<gff, 256>>>(h2, W1, m1, b1, nullptr, N_NODES, D_FF, D_MODEL);
    sgemm_k<EPI_BIAS_RES><<<g512, 256>>>(m1, W2, tf, b2, x1, N_NODES, D_MODEL, D_FF);

    // ---- merge ----
    concat_k<<<(N_NODES * D_MODEL / 4) / 256, 256>>>();
    sgemm_k<EPI_BIAS_RES><<<g512, 256>>>(cat, Wa, out, ba, x, N_NODES, D_MODEL, 2 * D_MODEL);
}

// round 4
// speedup vs baseline: 3.0572x; 3.0572x over previous
#include <cuda_runtime.h>
#include <cuda_bf16.h>
#include <math.h>

#define N_NODES 4096
#define D_MODEL 512
#define N_HEADS 8
#define D_HEAD  64
#define D_FF    2048
#define N_EDGES 65536

#define EPI_NONE      0
#define EPI_BIAS      1
#define EPI_BIAS_GELU 2
#define EPI_BIAS_RES  3

#define PITCH 80   // bytes per 32-bf16 smem row (64B data + 16B pad): conflict-free ldmatrix

// ---------------- scratch (static device globals; no allocations) ----------------
__device__ float g_xt [N_NODES * D_MODEL];
__device__ float g_mp [N_NODES * D_MODEL];
__device__ float g_dinv[N_NODES];
__device__ float g_h  [N_NODES * D_MODEL];
__device__ float g_q  [N_NODES * D_MODEL];
__device__ float g_k  [N_NODES * D_MODEL];
__device__ float g_v  [N_NODES * D_MODEL];
__device__ float g_o  [N_NODES * D_MODEL];
__device__ float g_x1 [N_NODES * D_MODEL];
__device__ float g_h2 [N_NODES * D_MODEL];
__device__ float g_m1 [N_NODES * D_FF];
__device__ float g_tf [N_NODES * D_MODEL];
__device__ float g_cat[N_NODES * 2 * D_MODEL];
__device__ float g_s  [(size_t)N_HEADS * N_NODES * N_NODES];   // 512 MB scores / probs

// ---------------- helpers ----------------
__device__ __forceinline__ float gelu_tanh(float x) {
    float x3 = x * x * x;
    float t  = tanhf(0.7978845608028654f * (x + 0.044715f * x3));
    return 0.5f * x * (1.0f + t);
}
__device__ __forceinline__ unsigned sm2u(const void* p) {
    unsigned a;
    asm("{ .reg .u64 t; cvta.to.shared.u64 t, %1; cvt.u32.u64 %0, t; }" : "=r"(a) : "l"(p));
    return a;
}
__device__ __forceinline__ void ldm4(unsigned addr, unsigned& r0, unsigned& r1,
                                     unsigned& r2, unsigned& r3) {
    asm volatile("ldmatrix.sync.aligned.m8n8.x4.shared.b16 {%0,%1,%2,%3}, [%4];"
                 : "=r"(r0), "=r"(r1), "=r"(r2), "=r"(r3) : "r"(addr));
}
__device__ __forceinline__ void hmma(float4& d, unsigned a0, unsigned a1,
                                     unsigned a2, unsigned a3,
                                     unsigned b0, unsigned b1) {
    asm volatile("mma.sync.aligned.m16n8k16.row.col.f32.bf16.bf16.f32 "
                 "{%0,%1,%2,%3}, {%4,%5,%6,%7}, {%8,%9}, {%0,%1,%2,%3};"
                 : "+f"(d.x), "+f"(d.y), "+f"(d.z), "+f"(d.w)
                 : "r"(a0), "r"(a1), "r"(a2), "r"(a3), "r"(b0), "r"(b1));
}
// split fp32 -> (hi, lo) bf16 pairs packed for 8B stores
__device__ __forceinline__ void cvt4(float x0, float x1, float x2, float x3,
                                     uint2& hi, uint2& lo) {
    __nv_bfloat16 h0 = __float2bfloat16(x0), h1 = __float2bfloat16(x1);
    __nv_bfloat16 h2 = __float2bfloat16(x2), h3 = __float2bfloat16(x3);
    __nv_bfloat16 l0 = __float2bfloat16(x0 - __bfloat162float(h0));
    __nv_bfloat16 l1 = __float2bfloat16(x1 - __bfloat162float(h1));
    __nv_bfloat16 l2 = __float2bfloat16(x2 - __bfloat162float(h2));
    __nv_bfloat16 l3 = __float2bfloat16(x3 - __bfloat162float(h3));
    hi.x = ((unsigned)__bfloat16_as_ushort(h1) << 16) | __bfloat16_as_ushort(h0);
    hi.y = ((unsigned)__bfloat16_as_ushort(h3) << 16) | __bfloat16_as_ushort(h2);
    lo.x = ((unsigned)__bfloat16_as_ushort(l1) << 16) | __bfloat16_as_ushort(l0);
    lo.y = ((unsigned)__bfloat16_as_ushort(l3) << 16) | __bfloat16_as_ushort(l2);
}

// ================= HMMA split-bf16 GEMM =================
// C[z][128 x TN] tile = A[z] @ B[z]   (A row-major, K contiguous)
// GATHER=true : B stored [K, N] row-major -> transpose-gather into smem B^T
// GATHER=false: B^T rows contiguous in memory (ldb stride between n-rows)
template<int TN, int EPI, bool GATHER>
__global__ __launch_bounds__(256)
void tgemm_k(const float* __restrict__ A, int lda, long long zA,
             const float* __restrict__ B, int ldb, long long zB,
             float* __restrict__ C, int ldc, long long zC,
             const float* __restrict__ bias,
             const float* __restrict__ res, int ldres,
             int K)
{
    extern __shared__ char smem[];
    const int tid  = threadIdx.x;
    const int lane = tid & 31;
    const int wid  = tid >> 5;
    const int wm   = wid & 3;          // 4 warp-rows of 32
    const int wn   = wid >> 2;         // 2 warp-cols of TN/2
    const int bm   = blockIdx.y * 128;
    const int bn   = blockIdx.x * TN;
    const int z    = blockIdx.z;
    A += (long long)z * zA;
    B += (long long)z * zB;
    C += (long long)z * zC;

    constexpr int APL = 128 * PITCH;   // A plane bytes
    constexpr int BPL = TN * PITCH;
    char* a_hi = smem;
    char* a_lo = smem + APL;
    char* b_hi = smem + 2 * APL;
    char* b_lo = smem + 2 * APL + BPL;
    const unsigned ua_hi = sm2u(a_hi), ua_lo = sm2u(a_lo);
    const unsigned ub_hi = sm2u(b_hi), ub_lo = sm2u(b_lo);

    constexpr int N8 = TN / 16;        // n8-tiles per warp
    float4 acc[2][N8];
    #pragma unroll
    for (int i = 0; i < 2; i++)
        #pragma unroll
        for (int j = 0; j < N8; j++) acc[i][j] = make_float4(0.f, 0.f, 0.f, 0.f);

    // per-lane ldmatrix address offsets (within plane)
    // A tile: lanes 0-15 -> rows m0+(l&15) @koff+0 ; lanes 16-31 -> same rows @koff+16
    const unsigned aoff = (unsigned)(wm * 32 + (lane & 15)) * PITCH + ((lane & 16) ? 16u : 0u);
    // B tile: rows n0 + (l&7) + ((l&16)?8:0) ; koff += ((l&8)?16:0)
    const unsigned boff = (unsigned)(wn * (TN / 2) + (lane & 7) + ((lane & 16) ? 8 : 0)) * PITCH
                        + ((lane & 8) ? 16u : 0u);

    for (int k0 = 0; k0 < K; k0 += 32) {
        // ---- fill A tile: 128 rows x 32 k ----
        #pragma unroll
        for (int i = tid; i < 1024; i += 256) {
            int r = i >> 3, c4 = (i & 7) << 2;
            float4 v = *(const float4*)(A + (size_t)(bm + r) * lda + k0 + c4);
            uint2 hv, lv; cvt4(v.x, v.y, v.z, v.w, hv, lv);
            unsigned off = r * PITCH + c4 * 2;
            *(uint2*)(a_hi + off) = hv;
            *(uint2*)(a_lo + off) = lv;
        }
        // ---- fill B^T tile: TN rows x 32 k ----
        if (GATHER) {
            #pragma unroll
            for (int i = tid; i < TN * 8; i += 256) {
                int n = i & (TN - 1), kg = i / TN;
                int kk = k0 + kg * 4;
                float s0 = B[(size_t)(kk + 0) * ldb + bn + n];
                float s1 = B[(size_t)(kk + 1) * ldb + bn + n];
                float s2 = B[(size_t)(kk + 2) * ldb + bn + n];
                float s3 = B[(size_t)(kk + 3) * ldb + bn + n];
                uint2 hv, lv; cvt4(s0, s1, s2, s3, hv, lv);
                unsigned off = n * PITCH + kg * 8;
                *(uint2*)(b_hi + off) = hv;
                *(uint2*)(b_lo + off) = lv;
            }
        } else {
            #pragma unroll
            for (int i = tid; i < TN * 8; i += 256) {
                int r = i >> 3, c4 = (i & 7) << 2;
                float4 v = *(const float4*)(B + (size_t)(bn + r) * ldb + k0 + c4);
                uint2 hv, lv; cvt4(v.x, v.y, v.z, v.w, hv, lv);
                unsigned off = r * PITCH + c4 * 2;
                *(uint2*)(b_hi + off) = hv;
                *(uint2*)(b_lo + off) = lv;
            }
        }
        __syncthreads();

        // ---- MMA over 2 k16 steps ----
        #pragma unroll
        for (int ks = 0; ks < 2; ks++) {
            const unsigned kb = ks * 32;
            unsigned ah[2][4], al[2][4];
            #pragma unroll
            for (int mt = 0; mt < 2; mt++) {
                unsigned ao = aoff + mt * 16 * PITCH + kb;
                ldm4(ua_hi + ao, ah[mt][0], ah[mt][1], ah[mt][2], ah[mt][3]);
                ldm4(ua_lo + ao, al[mt][0], al[mt][1], al[mt][2], al[mt][3]);
            }
            #pragma unroll
            for (int np = 0; np < N8 / 2; np++) {
                unsigned bo = boff + np * 16 * PITCH + kb;
                unsigned bh[4], bl[4];
                ldm4(ub_hi + bo, bh[0], bh[1], bh[2], bh[3]);
                ldm4(ub_lo + bo, bl[0], bl[1], bl[2], bl[3]);
                #pragma unroll
                for (int mt = 0; mt < 2; mt++) {
                    hmma(acc[mt][2*np  ], ah[mt][0], ah[mt][1], ah[mt][2], ah[mt][3], bh[0], bh[1]);
                    hmma(acc[mt][2*np+1], ah[mt][0], ah[mt][1], ah[mt][2], ah[mt][3], bh[2], bh[3]);
                    hmma(acc[mt][2*np  ], ah[mt][0], ah[mt][1], ah[mt][2], ah[mt][3], bl[0], bl[1]);
                    hmma(acc[mt][2*np+1], ah[mt][0], ah[mt][1], ah[mt][2], ah[mt][3], bl[2], bl[3]);
                    hmma(acc[mt][2*np  ], al[mt][0], al[mt][1], al[mt][2], al[mt][3], bh[0], bh[1]);
                    hmma(acc[mt][2*np+1], al[mt][0], al[mt][1], al[mt][2], al[mt][3], bh[2], bh[3]);
                }
            }
        }
        __syncthreads();
    }

    // ---- epilogue ----
    const int qr = lane >> 2;            // 0..7
    const int qc = (lane & 3) << 1;      // 0,2,4,6
    #pragma unroll
    for (int mt = 0; mt < 2; mt++) {
        #pragma unroll
        for (int nt = 0; nt < N8; nt++) {
            int col = bn + wn * (TN / 2) + nt * 8 + qc;
            float2 bb = make_float2(0.f, 0.f);
            if (EPI != EPI_NONE) bb = *(const float2*)&bias[col];
            #pragma unroll
            for (int half = 0; half < 2; half++) {
                int row = bm + wm * 32 + mt * 16 + qr + half * 8;
                float2 v;
                v.x = half ? acc[mt][nt].z : acc[mt][nt].x;
                v.y = half ? acc[mt][nt].w : acc[mt][nt].y;
                if (EPI != EPI_NONE) { v.x += bb.x; v.y += bb.y; }
                if (EPI == EPI_BIAS_GELU) { v.x = gelu_tanh(v.x); v.y = gelu_tanh(v.y); }
                if (EPI == EPI_BIAS_RES) {
                    float2 rr = *(const float2*)&res[(size_t)row * ldres + col];
                    v.x += rr.x; v.y += rr.y;
                }
                *(float2*)&C[(size_t)row * ldc + col] = v;
            }
        }
    }
}

// ---------------- row softmax over S (in place), scale 1/sqrt(64) -------------
__global__ __launch_bounds__(256)
void softmax_k(float* __restrict__ S)
{
    const size_t row = blockIdx.x;
    float4* p = (float4*)(S + row * (size_t)N_NODES);
    const int tid = threadIdx.x, lane = tid & 31, wid = tid >> 5;
    __shared__ float red[8];
    __shared__ float s_m, s_inv;

    float4 v[4];
    float mx = -1e30f;
    #pragma unroll
    for (int i = 0; i < 4; i++) {
        v[i] = p[tid + 256 * i];
        mx = fmaxf(mx, fmaxf(fmaxf(v[i].x, v[i].y), fmaxf(v[i].z, v[i].w)));
    }
    #pragma unroll
    for (int off = 16; off > 0; off >>= 1)
        mx = fmaxf(mx, __shfl_xor_sync(0xffffffffu, mx, off));
    if (lane == 0) red[wid] = mx;
    __syncthreads();
    if (tid == 0) {
        float m = red[0];
        #pragma unroll
        for (int i = 1; i < 8; i++) m = fmaxf(m, red[i]);
        s_m = m;
    }
    __syncthreads();
    mx = s_m;

    float sum = 0.0f;
    #pragma unroll
    for (int i = 0; i < 4; i++) {
        v[i].x = __expf(0.125f * (v[i].x - mx));
        v[i].y = __expf(0.125f * (v[i].y - mx));
        v[i].z = __expf(0.125f * (v[i].z - mx));
        v[i].w = __expf(0.125f * (v[i].w - mx));
        sum += v[i].x + v[i].y + v[i].z + v[i].w;
    }
    #pragma unroll
    for (int off = 16; off > 0; off >>= 1)
        sum += __shfl_xor_sync(0xffffffffu, sum, off);
    if (lane == 0) red[wid] = sum;
    __syncthreads();
    if (tid == 0) {
        float t = 0.f;
        #pragma unroll
        for (int i = 0; i < 8; i++) t += red[i];
        s_inv = 1.0f / t;
    }
    __syncthreads();
    float inv = s_inv;
    #pragma unroll
    for (int i = 0; i < 4; i++) {
        v[i].x *= inv; v[i].y *= inv; v[i].z *= inv; v[i].w *= inv;
        p[tid + 256 * i] = v[i];
    }
}

// ---------------- LayerNorm over last dim (512) ----------------
__global__ void ln_k(const float* __restrict__ x, const float* __restrict__ s,
                     const float* __restrict__ b, float* __restrict__ y)
{
    const int row = blockIdx.x;
    const int tid = threadIdx.x;   // 256
    const float* xr = x + (size_t)row * D_MODEL;

    float v0 = xr[tid];
    float v1 = xr[tid + 256];
    float sum = v0 + v1;
    float sq  = v0 * v0 + v1 * v1;

#pragma unroll
    for (int off = 16; off > 0; off >>= 1) {
        sum += __shfl_xor_sync(0xffffffffu, sum, off);
        sq  += __shfl_xor_sync(0xffffffffu, sq,  off);
    }
    __shared__ float rs[8], rq[8];
    __shared__ float s_mean, s_inv;
    if ((tid & 31) == 0) { rs[tid >> 5] = sum; rq[tid >> 5] = sq; }
    __syncthreads();
    if (tid == 0) {
        float ts = 0.f, tq = 0.f;
#pragma unroll
        for (int i = 0; i < 8; i++) { ts += rs[i]; tq += rq[i]; }
        float mean = ts * (1.0f / D_MODEL);
        float var  = tq * (1.0f / D_MODEL) - mean * mean;
        s_mean = mean;
        s_inv  = rsqrtf(var + 1e-5f);
    }
    __syncthreads();
    float mean = s_mean, inv = s_inv;
    float* yr = y + (size_t)row * D_MODEL;
    yr[tid]       = (v0 - mean) * inv * s[tid]       + b[tid];
    yr[tid + 256] = (v1 - mean) * inv * s[tid + 256] + b[tid + 256];
}

// ---------------- GCN kernels ----------------
__global__ void deg_init_k() {
    int i = blockIdx.x * blockDim.x + threadIdx.x;
    if (i < N_NODES) g_dinv[i] = 1.0f;
}
__global__ void deg_acc_k(const int* __restrict__ ei, const float* __restrict__ ew) {
    int e = blockIdx.x * blockDim.x + threadIdx.x;
    if (e < N_EDGES) atomicAdd(&g_dinv[ei[N_EDGES + e]], ew[e]);
}
__global__ void deg_fin_k() {
    int i = blockIdx.x * blockDim.x + threadIdx.x;
    if (i < N_NODES) g_dinv[i] = rsqrtf(g_dinv[i]);
}
__global__ void mp_init_k(const float* __restrict__ bg) {
    int idx = blockIdx.x * blockDim.x + threadIdx.x;
    int n  = idx >> 7;
    int d4 = (idx & 127) << 2;
    float di = g_dinv[n];
    float c  = di * di;
    float4 xv = *(const float4*)&g_xt[(size_t)n * D_MODEL + d4];
    float4 bb = *(const float4*)&bg[d4];
    float4 r;
    r.x = fmaf(xv.x, c, bb.x); r.y = fmaf(xv.y, c, bb.y);
    r.z = fmaf(xv.z, c, bb.z); r.w = fmaf(xv.w, c, bb.w);
    *(float4*)&g_mp[(size_t)n * D_MODEL + d4] = r;
}
__global__ void scatter_k(const int* __restrict__ ei, const float* __restrict__ ew) {
    int idx = blockIdx.x * blockDim.x + threadIdx.x;
    int e  = idx >> 7;
    int d4 = (idx & 127) << 2;
    int s  = ei[e];
    int t  = ei[N_EDGES + e];
    float coef = g_dinv[s] * ew[e] * g_dinv[t];
    float4 xv = *(const float4*)&g_xt[(size_t)s * D_MODEL + d4];
    float* dstp = &g_mp[(size_t)t * D_MODEL + d4];
    atomicAdd(dstp + 0, xv.x * coef);
    atomicAdd(dstp + 1, xv.y * coef);
    atomicAdd(dstp + 2, xv.z * coef);
    atomicAdd(dstp + 3, xv.w * coef);
}

// ---------------- concat [mp | tf] -> cat [N, 1024] ----------------
__global__ void concat_k() {
    int idx = blockIdx.x * blockDim.x + threadIdx.x;
    int n  = idx >> 7;
    int d4 = (idx & 127) << 2;
    float4 a = *(const float4*)&g_mp[(size_t)n * D_MODEL + d4];
    float4 b = *(const float4*)&g_tf[(size_t)n * D_MODEL + d4];
    *(float4*)&g_cat[(size_t)n * (2 * D_MODEL) + d4]           = a;
    *(float4*)&g_cat[(size_t)n * (2 * D_MODEL) + D_MODEL + d4] = b;
}

// ---------------- launch ----------------
extern "C" void kernel_launch(void* const* d_in, const int* in_sizes, int n_in,
                              void* d_out, int out_size)
{
    (void)in_sizes; (void)n_in; (void)out_size;
    const float* x     = (const float*)d_in[0];
    const int*   ei    = (const int*)  d_in[1];
    const float* ew    = (const float*)d_in[2];
    const float* Wg    = (const float*)d_in[3];
    const float* bg    = (const float*)d_in[4];
    const float* ln1_s = (const float*)d_in[5];
    const float* ln1_b = (const float*)d_in[6];
    const float* Wq    = (const float*)d_in[7];
    const float* bq    = (const float*)d_in[8];
    const float* Wk    = (const float*)d_in[9];
    const float* bk    = (const float*)d_in[10];
    const float* Wv    = (const float*)d_in[11];
    const float* bv    = (const float*)d_in[12];
    const float* Wo    = (const float*)d_in[13];
    const float* bo    = (const float*)d_in[14];
    const float* ln2_s = (const float*)d_in[15];
    const float* ln2_b = (const float*)d_in[16];
    const float* W1    = (const float*)d_in[17];
    const float* b1    = (const float*)d_in[18];
    const float* W2    = (const float*)d_in[19];
    const float* b2    = (const float*)d_in[20];
    const float* Wa    = (const float*)d_in[21];
    const float* ba    = (const float*)d_in[22];
    float* out = (float*)d_out;

    float *xt, *h, *q, *k, *v, *o, *x1, *h2, *m1, *tf, *cat, *s;
    cudaGetSymbolAddress((void**)&xt,  g_xt);
    cudaGetSymbolAddress((void**)&h,   g_h);
    cudaGetSymbolAddress((void**)&q,   g_q);
    cudaGetSymbolAddress((void**)&k,   g_k);
    cudaGetSymbolAddress((void**)&v,   g_v);
    cudaGetSymbolAddress((void**)&o,   g_o);
    cudaGetSymbolAddress((void**)&x1,  g_x1);
    cudaGetSymbolAddress((void**)&h2,  g_h2);
    cudaGetSymbolAddress((void**)&m1,  g_m1);
    cudaGetSymbolAddress((void**)&tf,  g_tf);
    cudaGetSymbolAddress((void**)&cat, g_cat);
    cudaGetSymbolAddress((void**)&s,   g_s);

    const int SM128 = 2 * (128 * PITCH) + 2 * (128 * PITCH);   // 40960
    const int SM64  = 2 * (128 * PITCH) + 2 * (64 * PITCH);    // 30720

    // ---- GCN branch ----
    tgemm_k<128, EPI_NONE, true><<<dim3(4, 32, 1), 256, SM128>>>(
        x, D_MODEL, 0, Wg, D_MODEL, 0, xt, D_MODEL, 0, nullptr, nullptr, 0, D_MODEL);
    deg_init_k<<<N_NODES / 256, 256>>>();
    deg_acc_k<<<N_EDGES / 256, 256>>>(ei, ew);
    deg_fin_k<<<N_NODES / 256, 256>>>();
    mp_init_k<<<(N_NODES * D_MODEL / 4) / 256, 256>>>(bg);
    scatter_k<<<(N_EDGES * (D_MODEL / 4)) / 256, 256>>>(ei, ew);

    // ---- Transformer branch ----
    ln_k<<<N_NODES, 256>>>(x, ln1_s, ln1_b, h);
    tgemm_k<128, EPI_BIAS, true><<<dim3(4, 32, 1), 256, SM128>>>(
        h, D_MODEL, 0, Wq, D_MODEL, 0, q, D_MODEL, 0, bq, nullptr, 0, D_MODEL);
    tgemm_k<128, EPI_BIAS, true><<<dim3(4, 32, 1), 256, SM128>>>(
        h, D_MODEL, 0, Wk, D_MODEL, 0, k, D_MODEL, 0, bk, nullptr, 0, D_MODEL);
    tgemm_k<128, EPI_BIAS, true><<<dim3(4, 32, 1), 256, SM128>>>(
        h, D_MODEL, 0, Wv, D_MODEL, 0, v, D_MODEL, 0, bv, nullptr, 0, D_MODEL);

    // S_h = Q_h K_h^T  (per head, raw logits)
    tgemm_k<128, EPI_NONE, false><<<dim3(32, 32, 8), 256, SM128>>>(
        q, D_MODEL, D_HEAD, k, D_MODEL, D_HEAD,
        s, N_NODES, (long long)N_NODES * N_NODES, nullptr, nullptr, 0, D_HEAD);
    softmax_k<<<N_HEADS * N_NODES, 256>>>(s);
    // O_h = P_h V_h
    tgemm_k<64, EPI_NONE, true><<<dim3(1, 32, 8), 256, SM64>>>(
        s, N_NODES, (long long)N_NODES * N_NODES, v, D_MODEL, D_HEAD,
        o, D_MODEL, D_HEAD, nullptr, nullptr, 0, N_NODES);

    tgemm_k<128, EPI_BIAS_RES, true><<<dim3(4, 32, 1), 256, SM128>>>(
        o, D_MODEL, 0, Wo, D_MODEL, 0, x1, D_MODEL, 0, bo, x, D_MODEL, D_MODEL);
    ln_k<<<N_NODES, 256>>>(x1, ln2_s, ln2_b, h2);
    tgemm_k<128, EPI_BIAS_GELU, true><<<dim3(16, 32, 1), 256, SM128>>>(
        h2, D_MODEL, 0, W1, D_FF, 0, m1, D_FF, 0, b1, nullptr, 0, D_MODEL);
    tgemm_k<128, EPI_BIAS_RES, true><<<dim3(4, 32, 1), 256, SM128>>>(
        m1, D_FF, 0, W2, D_MODEL, 0, tf, D_MODEL, 0, b2, x1, D_MODEL, D_FF);

    // ---- merge ----
    concat_k<<<(N_NODES * D_MODEL / 4) / 256, 256>>>();
    tgemm_k<128, EPI_BIAS_RES, true><<<dim3(4, 32, 1), 256, SM128>>>(
        cat, 2 * D_MODEL, 0, Wa, D_MODEL, 0, out, D_MODEL, 0, ba, x, D_MODEL, 2 * D_MODEL);
}

// round 8
// speedup vs baseline: 4.0466x; 1.3236x over previous
#include <cuda_runtime.h>
#include <cuda_bf16.h>
#include <math.h>

#define N_NODES 4096
#define D_MODEL 512
#define N_HEADS 8
#define D_HEAD  64
#define D_FF    2048
#define N_EDGES 65536

#define EPI_NONE      0
#define EPI_BIAS      1
#define EPI_BIAS_GELU 2
#define EPI_BIAS_RES  3

#define PITCH 80   // GEMM smem pitch: 32 bf16 (64B) + 16B pad

// ---------------- scratch (static device globals; no allocations) ----------------
__device__ float g_xt [N_NODES * D_MODEL];
__device__ float g_mp [N_NODES * D_MODEL];
__device__ float g_dinv[N_NODES];
__device__ float g_h  [N_NODES * D_MODEL];
__device__ float g_q  [N_NODES * D_MODEL];
__device__ float g_k  [N_NODES * D_MODEL];
__device__ float g_v  [N_NODES * D_MODEL];
__device__ float g_o  [N_NODES * D_MODEL];
__device__ float g_x1 [N_NODES * D_MODEL];
__device__ float g_h2 [N_NODES * D_MODEL];
__device__ float g_m1 [N_NODES * D_FF];
__device__ float g_tf [N_NODES * D_MODEL];
__device__ float g_cat[N_NODES * 2 * D_MODEL];

// ---------------- helpers ----------------
__device__ __forceinline__ float gelu_tanh(float x) {
    float x3 = x * x * x;
    float t  = tanhf(0.7978845608028654f * (x + 0.044715f * x3));
    return 0.5f * x * (1.0f + t);
}
__device__ __forceinline__ unsigned sm2u(const void* p) {
    unsigned a;
    asm("{ .reg .u64 t; cvta.to.shared.u64 t, %1; cvt.u32.u64 %0, t; }" : "=r"(a) : "l"(p));
    return a;
}
__device__ __forceinline__ void ldm4(unsigned addr, unsigned& r0, unsigned& r1,
                                     unsigned& r2, unsigned& r3) {
    asm volatile("ldmatrix.sync.aligned.m8n8.x4.shared.b16 {%0,%1,%2,%3}, [%4];"
                 : "=r"(r0), "=r"(r1), "=r"(r2), "=r"(r3) : "r"(addr));
}
__device__ __forceinline__ void ldm4t(unsigned addr, unsigned& r0, unsigned& r1,
                                      unsigned& r2, unsigned& r3) {
    asm volatile("ldmatrix.sync.aligned.m8n8.x4.trans.shared.b16 {%0,%1,%2,%3}, [%4];"
                 : "=r"(r0), "=r"(r1), "=r"(r2), "=r"(r3) : "r"(addr));
}
__device__ __forceinline__ void hmma(float4& d, unsigned a0, unsigned a1,
                                     unsigned a2, unsigned a3,
                                     unsigned b0, unsigned b1) {
    asm volatile("mma.sync.aligned.m16n8k16.row.col.f32.bf16.bf16.f32 "
                 "{%0,%1,%2,%3}, {%4,%5,%6,%7}, {%8,%9}, {%0,%1,%2,%3};"
                 : "+f"(d.x), "+f"(d.y), "+f"(d.z), "+f"(d.w)
                 : "r"(a0), "r"(a1), "r"(a2), "r"(a3), "r"(b0), "r"(b1));
}
// split fp32 -> (hi, lo) bf16 pairs packed for 8B stores
__device__ __forceinline__ void cvt4(float x0, float x1, float x2, float x3,
                                     uint2& hi, uint2& lo) {
    __nv_bfloat16 h0 = __float2bfloat16(x0), h1 = __float2bfloat16(x1);
    __nv_bfloat16 h2 = __float2bfloat16(x2), h3 = __float2bfloat16(x3);
    __nv_bfloat16 l0 = __float2bfloat16(x0 - __bfloat162float(h0));
    __nv_bfloat16 l1 = __float2bfloat16(x1 - __bfloat162float(h1));
    __nv_bfloat16 l2 = __float2bfloat16(x2 - __bfloat162float(h2));
    __nv_bfloat16 l3 = __float2bfloat16(x3 - __bfloat162float(h3));
    hi.x = ((unsigned)__bfloat16_as_ushort(h1) << 16) | __bfloat16_as_ushort(h0);
    hi.y = ((unsigned)__bfloat16_as_ushort(h3) << 16) | __bfloat16_as_ushort(h2);
    lo.x = ((unsigned)__bfloat16_as_ushort(l1) << 16) | __bfloat16_as_ushort(l0);
    lo.y = ((unsigned)__bfloat16_as_ushort(l3) << 16) | __bfloat16_as_ushort(l2);
}
// pack two floats -> bf16x2 hi + bf16x2 lo
__device__ __forceinline__ void cvt2(float x, float y, unsigned& hi, unsigned& lo) {
    __nv_bfloat16 hx = __float2bfloat16(x), hy = __float2bfloat16(y);
    __nv_bfloat16 lx = __float2bfloat16(x - __bfloat162float(hx));
    __nv_bfloat16 ly = __float2bfloat16(y - __bfloat162float(hy));
    hi = ((unsigned)__bfloat16_as_ushort(hy) << 16) | __bfloat16_as_ushort(hx);
    lo = ((unsigned)__bfloat16_as_ushort(ly) << 16) | __bfloat16_as_ushort(lx);
}

// ================= HMMA split-bf16 GEMM (unchanged from R4) =================
template<int TN, int EPI, bool GATHER>
__global__ __launch_bounds__(256)
void tgemm_k(const float* __restrict__ A, int lda, long long zA,
             const float* __restrict__ B, int ldb, long long zB,
             float* __restrict__ C, int ldc, long long zC,
             const float* __restrict__ bias,
             const float* __restrict__ res, int ldres,
             int K)
{
    extern __shared__ char smem[];
    const int tid  = threadIdx.x;
    const int lane = tid & 31;
    const int wid  = tid >> 5;
    const int wm   = wid & 3;
    const int wn   = wid >> 2;
    const int bm   = blockIdx.y * 128;
    const int bn   = blockIdx.x * TN;
    const int z    = blockIdx.z;
    A += (long long)z * zA;
    B += (long long)z * zB;
    C += (long long)z * zC;

    constexpr int APL = 128 * PITCH;
    constexpr int BPL = TN * PITCH;
    char* a_hi = smem;
    char* a_lo = smem + APL;
    char* b_hi = smem + 2 * APL;
    char* b_lo = smem + 2 * APL + BPL;
    const unsigned ua_hi = sm2u(a_hi), ua_lo = sm2u(a_lo);
    const unsigned ub_hi = sm2u(b_hi), ub_lo = sm2u(b_lo);

    constexpr int N8 = TN / 16;
    float4 acc[2][N8];
    #pragma unroll
    for (int i = 0; i < 2; i++)
        #pragma unroll
        for (int j = 0; j < N8; j++) acc[i][j] = make_float4(0.f, 0.f, 0.f, 0.f);

    const unsigned aoff = (unsigned)(wm * 32 + (lane & 15)) * PITCH + ((lane & 16) ? 16u : 0u);
    const unsigned boff = (unsigned)(wn * (TN / 2) + (lane & 7) + ((lane & 16) ? 8 : 0)) * PITCH
                        + ((lane & 8) ? 16u : 0u);

    for (int k0 = 0; k0 < K; k0 += 32) {
        #pragma unroll
        for (int i = tid; i < 1024; i += 256) {
            int r = i >> 3, c4 = (i & 7) << 2;
            float4 v = *(const float4*)(A + (size_t)(bm + r) * lda + k0 + c4);
            uint2 hv, lv; cvt4(v.x, v.y, v.z, v.w, hv, lv);
            unsigned off = r * PITCH + c4 * 2;
            *(uint2*)(a_hi + off) = hv;
            *(uint2*)(a_lo + off) = lv;
        }
        if (GATHER) {
            #pragma unroll
            for (int i = tid; i < TN * 8; i += 256) {
                int n = i & (TN - 1), kg = i / TN;
                int kk = k0 + kg * 4;
                float s0 = B[(size_t)(kk + 0) * ldb + bn + n];
                float s1 = B[(size_t)(kk + 1) * ldb + bn + n];
                float s2 = B[(size_t)(kk + 2) * ldb + bn + n];
                float s3 = B[(size_t)(kk + 3) * ldb + bn + n];
                uint2 hv, lv; cvt4(s0, s1, s2, s3, hv, lv);
                unsigned off = n * PITCH + kg * 8;
                *(uint2*)(b_hi + off) = hv;
                *(uint2*)(b_lo + off) = lv;
            }
        } else {
            #pragma unroll
            for (int i = tid; i < TN * 8; i += 256) {
                int r = i >> 3, c4 = (i & 7) << 2;
                float4 v = *(const float4*)(B + (size_t)(bn + r) * ldb + k0 + c4);
                uint2 hv, lv; cvt4(v.x, v.y, v.z, v.w, hv, lv);
                unsigned off = r * PITCH + c4 * 2;
                *(uint2*)(b_hi + off) = hv;
                *(uint2*)(b_lo + off) = lv;
            }
        }
        __syncthreads();

        #pragma unroll
        for (int ks = 0; ks < 2; ks++) {
            const unsigned kb = ks * 32;
            unsigned ah[2][4], al[2][4];
            #pragma unroll
            for (int mt = 0; mt < 2; mt++) {
                unsigned ao = aoff + mt * 16 * PITCH + kb;
                ldm4(ua_hi + ao, ah[mt][0], ah[mt][1], ah[mt][2], ah[mt][3]);
                ldm4(ua_lo + ao, al[mt][0], al[mt][1], al[mt][2], al[mt][3]);
            }
            #pragma unroll
            for (int np = 0; np < N8 / 2; np++) {
                unsigned bo = boff + np * 16 * PITCH + kb;
                unsigned bh[4], bl[4];
                ldm4(ub_hi + bo, bh[0], bh[1], bh[2], bh[3]);
                ldm4(ub_lo + bo, bl[0], bl[1], bl[2], bl[3]);
                #pragma unroll
                for (int mt = 0; mt < 2; mt++) {
                    hmma(acc[mt][2*np  ], ah[mt][0], ah[mt][1], ah[mt][2], ah[mt][3], bh[0], bh[1]);
                    hmma(acc[mt][2*np+1], ah[mt][0], ah[mt][1], ah[mt][2], ah[mt][3], bh[2], bh[3]);
                    hmma(acc[mt][2*np  ], ah[mt][0], ah[mt][1], ah[mt][2], ah[mt][3], bl[0], bl[1]);
                    hmma(acc[mt][2*np+1], ah[mt][0], ah[mt][1], ah[mt][2], ah[mt][3], bl[2], bl[3]);
                    hmma(acc[mt][2*np  ], al[mt][0], al[mt][1], al[mt][2], al[mt][3], bh[0], bh[1]);
                    hmma(acc[mt][2*np+1], al[mt][0], al[mt][1], al[mt][2], al[mt][3], bh[2], bh[3]);
                }
            }
        }
        __syncthreads();
    }

    const int qr = lane >> 2;
    const int qc = (lane & 3) << 1;
    #pragma unroll
    for (int mt = 0; mt < 2; mt++) {
        #pragma unroll
        for (int nt = 0; nt < N8; nt++) {
            int col = bn + wn * (TN / 2) + nt * 8 + qc;
            float2 bb = make_float2(0.f, 0.f);
            if (EPI != EPI_NONE) bb = *(const float2*)&bias[col];
            #pragma unroll
            for (int half = 0; half < 2; half++) {
                int row = bm + wm * 32 + mt * 16 + qr + half * 8;
                float2 v;
                v.x = half ? acc[mt][nt].z : acc[mt][nt].x;
                v.y = half ? acc[mt][nt].w : acc[mt][nt].y;
                if (EPI != EPI_NONE) { v.x += bb.x; v.y += bb.y; }
                if (EPI == EPI_BIAS_GELU) { v.x = gelu_tanh(v.x); v.y = gelu_tanh(v.y); }
                if (EPI == EPI_BIAS_RES) {
                    float2 rr = *(const float2*)&res[(size_t)row * ldres + col];
                    v.x += rr.x; v.y += rr.y;
                }
                *(float2*)&C[(size_t)row * ldc + col] = v;
            }
        }
    }
}

// ================= fused flash attention (HMMA split-bf16) =================
// grid (32 q-tiles, 8 heads), 256 threads = 8 warps, warp w owns rows w*16..w*16+15
#define FPITCH 144            // bytes per 64-bf16 row (128B data + 16B pad)
#define QPL (128 * FPITCH)    // 18432
#define KPL (64 * FPITCH)     // 9216
#define FLASH_SMEM (2 * QPL + 4 * KPL)   // 73728

__global__ __launch_bounds__(256, 2)
void flash_k(const float* __restrict__ Q, const float* __restrict__ K,
             const float* __restrict__ V, float* __restrict__ O)
{
    extern __shared__ char sm[];
    char* qh = sm;
    char* ql = sm + QPL;
    char* kh = sm + 2 * QPL;
    char* kl = kh + KPL;
    char* vh = kl + KPL;
    char* vl = vh + KPL;
    const unsigned uqh = sm2u(qh), uql = sm2u(ql);
    const unsigned ukh = sm2u(kh), ukl = sm2u(kl);
    const unsigned uvh = sm2u(vh), uvl = sm2u(vl);

    const int tid  = threadIdx.x;
    const int lane = tid & 31;
    const int wid  = tid >> 5;
    const int h    = blockIdx.y;
    const int bq   = blockIdx.x * 128;
    const int hc   = h * D_HEAD;

    // load + scale + split Q tile [128 x 64]
    for (int i = tid; i < 2048; i += 256) {
        int r = i >> 4, c4 = (i & 15) << 2;
        float4 v = *(const float4*)&Q[(size_t)(bq + r) * D_MODEL + hc + c4];
        v.x *= 0.125f; v.y *= 0.125f; v.z *= 0.125f; v.w *= 0.125f;
        uint2 hv, lv; cvt4(v.x, v.y, v.z, v.w, hv, lv);
        unsigned off = r * FPITCH + c4 * 2;
        *(uint2*)(qh + off) = hv;
        *(uint2*)(ql + off) = lv;
    }

    const unsigned aoff = (unsigned)(wid * 16 + (lane & 15)) * FPITCH + ((lane & 16) ? 16u : 0u);
    const unsigned boff = (unsigned)((lane & 7) + ((lane & 16) ? 8 : 0)) * FPITCH
                        + ((lane & 8) ? 16u : 0u);
    const unsigned voff = (unsigned)((lane & 7) + ((lane & 8) ? 8 : 0)) * FPITCH
                        + ((lane & 16) ? 16u : 0u);

    float4 oacc[8];
    #pragma unroll
    for (int t = 0; t < 8; t++) oacc[t] = make_float4(0.f, 0.f, 0.f, 0.f);
    float m0 = -1e30f, m1 = -1e30f, l0 = 0.f, l1 = 0.f;

    for (int kb = 0; kb < N_NODES; kb += 64) {
        __syncthreads();
        // load + split K,V tiles [64 x 64]
        for (int i = tid; i < 1024; i += 256) {
            int r = i >> 4, c4 = (i & 15) << 2;
            size_t gofs = (size_t)(kb + r) * D_MODEL + hc + c4;
            unsigned off = r * FPITCH + c4 * 2;
            float4 a = *(const float4*)&K[gofs];
            uint2 hv, lv; cvt4(a.x, a.y, a.z, a.w, hv, lv);
            *(uint2*)(kh + off) = hv; *(uint2*)(kl + off) = lv;
            float4 b = *(const float4*)&V[gofs];
            cvt4(b.x, b.y, b.z, b.w, hv, lv);
            *(uint2*)(vh + off) = hv; *(uint2*)(vl + off) = lv;
        }
        __syncthreads();

        // ---- S = Q K^T : warp m16 x n64, k64 ----
        float4 sacc[8];
        #pragma unroll
        for (int t = 0; t < 8; t++) sacc[t] = make_float4(0.f, 0.f, 0.f, 0.f);
        #pragma unroll
        for (int t = 0; t < 4; t++) {
            unsigned ao = aoff + t * 32;
            unsigned ah[4], al[4];
            ldm4(uqh + ao, ah[0], ah[1], ah[2], ah[3]);
            ldm4(uql + ao, al[0], al[1], al[2], al[3]);
            #pragma unroll
            for (int ng = 0; ng < 4; ng++) {
                unsigned bo = boff + ng * (16 * FPITCH) + t * 32;
                unsigned bh[4], bl[4];
                ldm4(ukh + bo, bh[0], bh[1], bh[2], bh[3]);
                ldm4(ukl + bo, bl[0], bl[1], bl[2], bl[3]);
                hmma(sacc[2*ng  ], ah[0], ah[1], ah[2], ah[3], bh[0], bh[1]);
                hmma(sacc[2*ng+1], ah[0], ah[1], ah[2], ah[3], bh[2], bh[3]);
                hmma(sacc[2*ng  ], ah[0], ah[1], ah[2], ah[3], bl[0], bl[1]);
                hmma(sacc[2*ng+1], ah[0], ah[1], ah[2], ah[3], bl[2], bl[3]);
                hmma(sacc[2*ng  ], al[0], al[1], al[2], al[3], bh[0], bh[1]);
                hmma(sacc[2*ng+1], al[0], al[1], al[2], al[3], bh[2], bh[3]);
            }
        }

        // ---- online softmax (rows r0 = qr, r1 = qr+8) ----
        float mx0 = -1e30f, mx1 = -1e30f;
        #pragma unroll
        for (int t = 0; t < 8; t++) {
            mx0 = fmaxf(mx0, fmaxf(sacc[t].x, sacc[t].y));
            mx1 = fmaxf(mx1, fmaxf(sacc[t].z, sacc[t].w));
        }
        mx0 = fmaxf(mx0, __shfl_xor_sync(0xffffffffu, mx0, 1));
        mx0 = fmaxf(mx0, __shfl_xor_sync(0xffffffffu, mx0, 2));
        mx1 = fmaxf(mx1, __shfl_xor_sync(0xffffffffu, mx1, 1));
        mx1 = fmaxf(mx1, __shfl_xor_sync(0xffffffffu, mx1, 2));
        float mn0 = fmaxf(m0, mx0), mn1 = fmaxf(m1, mx1);
        float c0 = __expf(m0 - mn0), c1 = __expf(m1 - mn1);
        m0 = mn0; m1 = mn1;

        unsigned pxyh[8], pxyl[8], pzwh[8], pzwl[8];
        float s0 = 0.f, s1 = 0.f;
        #pragma unroll
        for (int t = 0; t < 8; t++) {
            float ex = __expf(sacc[t].x - mn0);
            float ey = __expf(sacc[t].y - mn0);
            float ez = __expf(sacc[t].z - mn1);
            float ew = __expf(sacc[t].w - mn1);
            s0 += ex + ey; s1 += ez + ew;
            cvt2(ex, ey, pxyh[t], pxyl[t]);
            cvt2(ez, ew, pzwh[t], pzwl[t]);
        }
        s0 += __shfl_xor_sync(0xffffffffu, s0, 1);
        s0 += __shfl_xor_sync(0xffffffffu, s0, 2);
        s1 += __shfl_xor_sync(0xffffffffu, s1, 1);
        s1 += __shfl_xor_sync(0xffffffffu, s1, 2);
        l0 = l0 * c0 + s0;
        l1 = l1 * c1 + s1;
        #pragma unroll
        for (int t = 0; t < 8; t++) {
            oacc[t].x *= c0; oacc[t].y *= c0;
            oacc[t].z *= c1; oacc[t].w *= c1;
        }

        // ---- O += P V : k64 over keys, n64 over dhead ----
        #pragma unroll
        for (int t = 0; t < 4; t++) {
            unsigned ah[4] = { pxyh[2*t], pzwh[2*t], pxyh[2*t+1], pzwh[2*t+1] };
            unsigned al[4] = { pxyl[2*t], pzwl[2*t], pxyl[2*t+1], pzwl[2*t+1] };
            #pragma unroll
            for (int ng = 0; ng < 4; ng++) {
                unsigned vo = voff + t * (16 * FPITCH) + ng * 32;
                unsigned bh[4], bl[4];
                ldm4t(uvh + vo, bh[0], bh[1], bh[2], bh[3]);
                ldm4t(uvl + vo, bl[0], bl[1], bl[2], bl[3]);
                hmma(oacc[2*ng  ], ah[0], ah[1], ah[2], ah[3], bh[0], bh[1]);
                hmma(oacc[2*ng+1], ah[0], ah[1], ah[2], ah[3], bh[2], bh[3]);
                hmma(oacc[2*ng  ], ah[0], ah[1], ah[2], ah[3], bl[0], bl[1]);
                hmma(oacc[2*ng+1], ah[0], ah[1], ah[2], ah[3], bl[2], bl[3]);
                hmma(oacc[2*ng  ], al[0], al[1], al[2], al[3], bh[0], bh[1]);
                hmma(oacc[2*ng+1], al[0], al[1], al[2], al[3], bh[2], bh[3]);
            }
        }
    }

    // ---- epilogue ----
    const int qr = lane >> 2;
    const int qc = (lane & 3) << 1;
    float inv0 = 1.0f / l0, inv1 = 1.0f / l1;
    int r0 = bq + wid * 16 + qr;
    int r1 = r0 + 8;
    #pragma unroll
    for (int t = 0; t < 8; t++) {
        int col = hc + t * 8 + qc;
        *(float2*)&O[(size_t)r0 * D_MODEL + col] =
            make_float2(oacc[t].x * inv0, oacc[t].y * inv0);
        *(float2*)&O[(size_t)r1 * D_MODEL + col] =
            make_float2(oacc[t].z * inv1, oacc[t].w * inv1);
    }
}

// ---------------- LayerNorm over last dim (512) ----------------
__global__ void ln_k(const float* __restrict__ x, const float* __restrict__ s,
                     const float* __restrict__ b, float* __restrict__ y)
{
    const int row = blockIdx.x;
    const int tid = threadIdx.x;   // 256
    const float* xr = x + (size_t)row * D_MODEL;

    float v0 = xr[tid];
    float v1 = xr[tid + 256];
    float sum = v0 + v1;
    float sq  = v0 * v0 + v1 * v1;

#pragma unroll
    for (int off = 16; off > 0; off >>= 1) {
        sum += __shfl_xor_sync(0xffffffffu, sum, off);
        sq  += __shfl_xor_sync(0xffffffffu, sq,  off);
    }
    __shared__ float rs[8], rq[8];
    __shared__ float s_mean, s_inv;
    if ((tid & 31) == 0) { rs[tid >> 5] = sum; rq[tid >> 5] = sq; }
    __syncthreads();
    if (tid == 0) {
        float ts = 0.f, tq = 0.f;
#pragma unroll
        for (int i = 0; i < 8; i++) { ts += rs[i]; tq += rq[i]; }
        float mean = ts * (1.0f / D_MODEL);
        float var  = tq * (1.0f / D_MODEL) - mean * mean;
        s_mean = mean;
        s_inv  = rsqrtf(var + 1e-5f);
    }
    __syncthreads();
    float mean = s_mean, inv = s_inv;
    float* yr = y + (size_t)row * D_MODEL;
    yr[tid]       = (v0 - mean) * inv * s[tid]       + b[tid];
    yr[tid + 256] = (v1 - mean) * inv * s[tid + 256] + b[tid + 256];
}

// ---------------- GCN kernels ----------------
__global__ void deg_init_k() {
    int i = blockIdx.x * blockDim.x + threadIdx.x;
    if (i < N_NODES) g_dinv[i] = 1.0f;
}
__global__ void deg_acc_k(const int* __restrict__ ei, const float* __restrict__ ew) {
    int e = blockIdx.x * blockDim.x + threadIdx.x;
    if (e < N_EDGES) atomicAdd(&g_dinv[ei[N_EDGES + e]], ew[e]);
}
__global__ void deg_fin_k() {
    int i = blockIdx.x * blockDim.x + threadIdx.x;
    if (i < N_NODES) g_dinv[i] = rsqrtf(g_dinv[i]);
}
__global__ void mp_init_k(const float* __restrict__ bg) {
    int idx = blockIdx.x * blockDim.x + threadIdx.x;
    int n  = idx >> 7;
    int d4 = (idx & 127) << 2;
    float di = g_dinv[n];
    float c  = di * di;
    float4 xv = *(const float4*)&g_xt[(size_t)n * D_MODEL + d4];
    float4 bb = *(const float4*)&bg[d4];
    float4 r;
    r.x = fmaf(xv.x, c, bb.x); r.y = fmaf(xv.y, c, bb.y);
    r.z = fmaf(xv.z, c, bb.z); r.w = fmaf(xv.w, c, bb.w);
    *(float4*)&g_mp[(size_t)n * D_MODEL + d4] = r;
}
__global__ void scatter_k(const int* __restrict__ ei, const float* __restrict__ ew) {
    int idx = blockIdx.x * blockDim.x + threadIdx.x;
    int e  = idx >> 7;
    int d4 = (idx & 127) << 2;
    int s  = ei[e];
    int t  = ei[N_EDGES + e];
    float coef = g_dinv[s] * ew[e] * g_dinv[t];
    float4 xv = *(const float4*)&g_xt[(size_t)s * D_MODEL + d4];
    float* dstp = &g_mp[(size_t)t * D_MODEL + d4];
    atomicAdd(dstp + 0, xv.x * coef);
    atomicAdd(dstp + 1, xv.y * coef);
    atomicAdd(dstp + 2, xv.z * coef);
    atomicAdd(dstp + 3, xv.w * coef);
}

// ---------------- concat [mp | tf] -> cat [N, 1024] ----------------
__global__ void concat_k() {
    int idx = blockIdx.x * blockDim.x + threadIdx.x;
    int n  = idx >> 7;
    int d4 = (idx & 127) << 2;
    float4 a = *(const float4*)&g_mp[(size_t)n * D_MODEL + d4];
    float4 b = *(const float4*)&g_tf[(size_t)n * D_MODEL + d4];
    *(float4*)&g_cat[(size_t)n * (2 * D_MODEL) + d4]           = a;
    *(float4*)&g_cat[(size_t)n * (2 * D_MODEL) + D_MODEL + d4] = b;
}

// ---------------- launch ----------------
extern "C" void kernel_launch(void* const* d_in, const int* in_sizes, int n_in,
                              void* d_out, int out_size)
{
    (void)in_sizes; (void)n_in; (void)out_size;
    const float* x     = (const float*)d_in[0];
    const int*   ei    = (const int*)  d_in[1];
    const float* ew    = (const float*)d_in[2];
    const float* Wg    = (const float*)d_in[3];
    const float* bg    = (const float*)d_in[4];
    const float* ln1_s = (const float*)d_in[5];
    const float* ln1_b = (const float*)d_in[6];
    const float* Wq    = (const float*)d_in[7];
    const float* bq    = (const float*)d_in[8];
    const float* Wk    = (const float*)d_in[9];
    const float* bk    = (const float*)d_in[10];
    const float* Wv    = (const float*)d_in[11];
    const float* bv    = (const float*)d_in[12];
    const float* Wo    = (const float*)d_in[13];
    const float* bo    = (const float*)d_in[14];
    const float* ln2_s = (const float*)d_in[15];
    const float* ln2_b = (const float*)d_in[16];
    const float* W1    = (const float*)d_in[17];
    const float* b1    = (const float*)d_in[18];
    const float* W2    = (const float*)d_in[19];
    const float* b2    = (const float*)d_in[20];
    const float* Wa    = (const float*)d_in[21];
    const float* ba    = (const float*)d_in[22];
    float* out = (float*)d_out;

    float *xt, *h, *q, *k, *v, *o, *x1, *h2, *m1, *tf, *cat;
    cudaGetSymbolAddress((void**)&xt,  g_xt);
    cudaGetSymbolAddress((void**)&h,   g_h);
    cudaGetSymbolAddress((void**)&q,   g_q);
    cudaGetSymbolAddress((void**)&k,   g_k);
    cudaGetSymbolAddress((void**)&v,   g_v);
    cudaGetSymbolAddress((void**)&o,   g_o);
    cudaGetSymbolAddress((void**)&x1,  g_x1);
    cudaGetSymbolAddress((void**)&h2,  g_h2);
    cudaGetSymbolAddress((void**)&m1,  g_m1);
    cudaGetSymbolAddress((void**)&tf,  g_tf);
    cudaGetSymbolAddress((void**)&cat, g_cat);

    const int SM128 = 2 * (128 * PITCH) + 2 * (128 * PITCH);   // 40960
    cudaFuncSetAttribute(flash_k, cudaFuncAttributeMaxDynamicSharedMemorySize, FLASH_SMEM);

    // ---- GCN branch ----
    tgemm_k<128, EPI_NONE, true><<<dim3(4, 32, 1), 256, SM128>>>(
        x, D_MODEL, 0, Wg, D_MODEL, 0, xt, D_MODEL, 0, nullptr, nullptr, 0, D_MODEL);
    deg_init_k<<<N_NODES / 256, 256>>>();
    deg_acc_k<<<N_EDGES / 256, 256>>>(ei, ew);
    deg_fin_k<<<N_NODES / 256, 256>>>();
    mp_init_k<<<(N_NODES * D_MODEL / 4) / 256, 256>>>(bg);
    scatter_k<<<(N_EDGES * (D_MODEL / 4)) / 256, 256>>>(ei, ew);

    // ---- Transformer branch ----
    ln_k<<<N_NODES, 256>>>(x, ln1_s, ln1_b, h);
    tgemm_k<128, EPI_BIAS, true><<<dim3(4, 32, 1), 256, SM128>>>(
        h, D_MODEL, 0, Wq, D_MODEL, 0, q, D_MODEL, 0, bq, nullptr, 0, D_MODEL);
    tgemm_k<128, EPI_BIAS, true><<<dim3(4, 32, 1), 256, SM128>>>(
        h, D_MODEL, 0, Wk, D_MODEL, 0, k, D_MODEL, 0, bk, nullptr, 0, D_MODEL);
    tgemm_k<128, EPI_BIAS, true><<<dim3(4, 32, 1), 256, SM128>>>(
        h, D_MODEL, 0, Wv, D_MODEL, 0, v, D_MODEL, 0, bv, nullptr, 0, D_MODEL);

    // fused flash attention
    flash_k<<<dim3(N_NODES / 128, N_HEADS), 256, FLASH_SMEM>>>(q, k, v, o);

    tgemm_k<128, EPI_BIAS_RES, true><<<dim3(4, 32, 1), 256, SM128>>>(
        o, D_MODEL, 0, Wo, D_MODEL, 0, x1, D_MODEL, 0, bo, x, D_MODEL, D_MODEL);
    ln_k<<<N_NODES, 256>>>(x1, ln2_s, ln2_b, h2);
    tgemm_k<128, EPI_BIAS_GELU, true><<<dim3(16, 32, 1), 256, SM128>>>(
        h2, D_MODEL, 0, W1, D_FF, 0, m1, D_FF, 0, b1, nullptr, 0, D_MODEL);
    tgemm_k<128, EPI_BIAS_RES, true><<<dim3(4, 32, 1), 256, SM128>>>(
        m1, D_FF, 0, W2, D_MODEL, 0, tf, D_MODEL, 0, b2, x1, D_MODEL, D_FF);

    // ---- merge ----
    concat_k<<<(N_NODES * D_MODEL / 4) / 256, 256>>>();
    tgemm_k<128, EPI_BIAS_RES, true><<<dim3(4, 32, 1), 256, SM128>>>(
        cat, 2 * D_MODEL, 0, Wa, D_MODEL, 0, out, D_MODEL, 0, ba, x, D_MODEL, 2 * D_MODEL);
}

// round 9
// speedup vs baseline: 4.8641x; 1.2020x over previous
#include <cuda_runtime.h>
#include <cuda_bf16.h>
#include <math.h>

#define N_NODES 4096
#define D_MODEL 512
#define N_HEADS 8
#define D_HEAD  64
#define D_FF    2048
#define N_EDGES 65536

#define EPI_NONE      0
#define EPI_BIAS      1
#define EPI_BIAS_GELU 2
#define EPI_BIAS_RES  3

#define PITCH 80   // GEMM smem pitch: 32 bf16 (64B) + 16B pad
typedef __nv_bfloat16 bf16;

// ---------------- fp32 scratch ----------------
__device__ float g_xt [N_NODES * D_MODEL];
__device__ float g_mp [N_NODES * D_MODEL];
__device__ float g_dinv[N_NODES];
__device__ float g_x1 [N_NODES * D_MODEL];
__device__ float g_tf [N_NODES * D_MODEL];

// ---------------- bf16 hi/lo activations ----------------
__device__ bf16 g_xbh[N_NODES * D_MODEL],  g_xbl[N_NODES * D_MODEL];
__device__ bf16 g_hh [N_NODES * D_MODEL],  g_hl [N_NODES * D_MODEL];
__device__ bf16 g_qh [N_NODES * D_MODEL],  g_ql [N_NODES * D_MODEL];
__device__ bf16 g_kh [N_NODES * D_MODEL],  g_kl [N_NODES * D_MODEL];
__device__ bf16 g_vh [N_NODES * D_MODEL],  g_vl [N_NODES * D_MODEL];
__device__ bf16 g_oh [N_NODES * D_MODEL],  g_ol [N_NODES * D_MODEL];
__device__ bf16 g_h2h[N_NODES * D_MODEL],  g_h2l[N_NODES * D_MODEL];
__device__ bf16 g_m1h[N_NODES * D_FF],     g_m1l[N_NODES * D_FF];
__device__ bf16 g_cth[N_NODES * 2*D_MODEL],g_ctl[N_NODES * 2*D_MODEL];

// ---------------- bf16 hi/lo transposed weights [N,K] ----------------
__device__ bf16 g_Wgh[D_MODEL*D_MODEL],  g_Wgl[D_MODEL*D_MODEL];
__device__ bf16 g_Wqh[D_MODEL*D_MODEL],  g_Wql[D_MODEL*D_MODEL];
__device__ bf16 g_Wkh[D_MODEL*D_MODEL],  g_Wkl[D_MODEL*D_MODEL];
__device__ bf16 g_Wvh[D_MODEL*D_MODEL],  g_Wvl[D_MODEL*D_MODEL];
__device__ bf16 g_Woh[D_MODEL*D_MODEL],  g_Wol[D_MODEL*D_MODEL];
__device__ bf16 g_W1h[D_MODEL*D_FF],     g_W1l[D_MODEL*D_FF];
__device__ bf16 g_W2h[D_FF*D_MODEL],     g_W2l[D_FF*D_MODEL];
__device__ bf16 g_Wah[2*D_MODEL*D_MODEL],g_Wal[2*D_MODEL*D_MODEL];

// ---------------- helpers ----------------
__device__ __forceinline__ float gelu_tanh(float x) {
    float x3 = x * x * x;
    float t  = tanhf(0.7978845608028654f * (x + 0.044715f * x3));
    return 0.5f * x * (1.0f + t);
}
__device__ __forceinline__ unsigned sm2u(const void* p) {
    unsigned a;
    asm("{ .reg .u64 t; cvta.to.shared.u64 t, %1; cvt.u32.u64 %0, t; }" : "=r"(a) : "l"(p));
    return a;
}
__device__ __forceinline__ void ldm4(unsigned addr, unsigned& r0, unsigned& r1,
                                     unsigned& r2, unsigned& r3) {
    asm volatile("ldmatrix.sync.aligned.m8n8.x4.shared.b16 {%0,%1,%2,%3}, [%4];"
                 : "=r"(r0), "=r"(r1), "=r"(r2), "=r"(r3) : "r"(addr));
}
__device__ __forceinline__ void ldm4t(unsigned addr, unsigned& r0, unsigned& r1,
                                      unsigned& r2, unsigned& r3) {
    asm volatile("ldmatrix.sync.aligned.m8n8.x4.trans.shared.b16 {%0,%1,%2,%3}, [%4];"
                 : "=r"(r0), "=r"(r1), "=r"(r2), "=r"(r3) : "r"(addr));
}
__device__ __forceinline__ void hmma(float4& d, unsigned a0, unsigned a1,
                                     unsigned a2, unsigned a3,
                                     unsigned b0, unsigned b1) {
    asm volatile("mma.sync.aligned.m16n8k16.row.col.f32.bf16.bf16.f32 "
                 "{%0,%1,%2,%3}, {%4,%5,%6,%7}, {%8,%9}, {%0,%1,%2,%3};"
                 : "+f"(d.x), "+f"(d.y), "+f"(d.z), "+f"(d.w)
                 : "r"(a0), "r"(a1), "r"(a2), "r"(a3), "r"(b0), "r"(b1));
}
__device__ __forceinline__ void cvt4(float x0, float x1, float x2, float x3,
                                     uint2& hi, uint2& lo) {
    bf16 h0 = __float2bfloat16(x0), h1 = __float2bfloat16(x1);
    bf16 h2 = __float2bfloat16(x2), h3 = __float2bfloat16(x3);
    bf16 l0 = __float2bfloat16(x0 - __bfloat162float(h0));
    bf16 l1 = __float2bfloat16(x1 - __bfloat162float(h1));
    bf16 l2 = __float2bfloat16(x2 - __bfloat162float(h2));
    bf16 l3 = __float2bfloat16(x3 - __bfloat162float(h3));
    hi.x = ((unsigned)__bfloat16_as_ushort(h1) << 16) | __bfloat16_as_ushort(h0);
    hi.y = ((unsigned)__bfloat16_as_ushort(h3) << 16) | __bfloat16_as_ushort(h2);
    lo.x = ((unsigned)__bfloat16_as_ushort(l1) << 16) | __bfloat16_as_ushort(l0);
    lo.y = ((unsigned)__bfloat16_as_ushort(l3) << 16) | __bfloat16_as_ushort(l2);
}
__device__ __forceinline__ void cvt2(float x, float y, unsigned& hi, unsigned& lo) {
    bf16 hx = __float2bfloat16(x), hy = __float2bfloat16(y);
    bf16 lx = __float2bfloat16(x - __bfloat162float(hx));
    bf16 ly = __float2bfloat16(y - __bfloat162float(hy));
    hi = ((unsigned)__bfloat16_as_ushort(hy) << 16) | __bfloat16_as_ushort(hx);
    lo = ((unsigned)__bfloat16_as_ushort(ly) << 16) | __bfloat16_as_ushort(lx);
}

#define CPA16(s, g)  asm volatile("cp.async.cg.shared.global [%0], [%1], 16;" :: "r"(s), "l"(g))
#define CPA_COMMIT() asm volatile("cp.async.commit_group;" ::: "memory")
#define CPA_WAIT1()  asm volatile("cp.async.wait_group 1;" ::: "memory")
#define CPA_WAIT0()  asm volatile("cp.async.wait_group 0;" ::: "memory")

// ================= prep kernels =================
// fp32 [K,N] -> transposed bf16 hi/lo [N,K]
__global__ void wprep_k(const float* __restrict__ W, bf16* __restrict__ hi,
                        bf16* __restrict__ lo, int K, int N)
{
    __shared__ float t[32][33];
    int k0 = blockIdx.y * 32, n0 = blockIdx.x * 32;
    int tx = threadIdx.x, ty = threadIdx.y;   // 32 x 8
    #pragma unroll
    for (int i = 0; i < 4; i++)
        t[ty + 8*i][tx] = W[(size_t)(k0 + ty + 8*i) * N + n0 + tx];
    __syncthreads();
    #pragma unroll
    for (int i = 0; i < 4; i++) {
        float v = t[tx][ty + 8*i];
        bf16 h = __float2bfloat16(v);
        bf16 l = __float2bfloat16(v - __bfloat162float(h));
        size_t o = (size_t)(n0 + ty + 8*i) * K + k0 + tx;
        hi[o] = h; lo[o] = l;
    }
}
// fp32 -> bf16 hi/lo elementwise (same layout)
__global__ void aprep_k(const float* __restrict__ x, bf16* __restrict__ hi,
                        bf16* __restrict__ lo)
{
    int idx = blockIdx.x * blockDim.x + threadIdx.x;
    float4 v = *(const float4*)(x + idx * 4);
    uint2 h, l; cvt4(v.x, v.y, v.z, v.w, h, l);
    *(uint2*)(hi + idx * 4) = h;
    *(uint2*)(lo + idx * 4) = l;
}

// ================= cp.async double-buffered HMMA split-bf16 GEMM =================
// C[128 x 128] tile = A[M,K](bf16 hi/lo) @ B[N,K](bf16 hi/lo, pre-transposed)^T
template<int EPI, bool OBF>
__global__ __launch_bounds__(256)
void tgemm2_k(const bf16* __restrict__ Ah, const bf16* __restrict__ Al, int lda,
              const bf16* __restrict__ Bh, const bf16* __restrict__ Bl,
              float* __restrict__ C, bf16* __restrict__ Ch, bf16* __restrict__ Cl,
              int ldc, const float* __restrict__ bias,
              const float* __restrict__ res, int ldres, int K, float scale)
{
    extern __shared__ char smem[];
    const int tid  = threadIdx.x;
    const int lane = tid & 31;
    const int wid  = tid >> 5;
    const int wm   = wid & 3;
    const int wn   = wid >> 2;
    const int bm   = blockIdx.y * 128;
    const int bn   = blockIdx.x * 128;

    constexpr int APL = 128 * PITCH;   // 10240 bytes per plane
    const unsigned us = sm2u(smem);

    const bf16* g0 = Ah + (size_t)bm * lda;
    const bf16* g1 = Al + (size_t)bm * lda;
    const bf16* g2 = Bh + (size_t)bn * K;
    const bf16* g3 = Bl + (size_t)bn * K;

    auto issue = [&](int b, int c) {
        const int k0 = c * 32;
        const unsigned sb = us + b * (4 * APL);
        #pragma unroll
        for (int i = tid; i < 512; i += 256) {
            int r = i >> 2, cc = i & 3;
            unsigned so = r * PITCH + cc * 16;
            size_t goA = (size_t)r * lda + k0 + cc * 8;
            size_t goB = (size_t)r * K   + k0 + cc * 8;
            CPA16(sb + 0*APL + so, g0 + goA);
            CPA16(sb + 1*APL + so, g1 + goA);
            CPA16(sb + 2*APL + so, g2 + goB);
            CPA16(sb + 3*APL + so, g3 + goB);
        }
        CPA_COMMIT();
    };

    float4 acc[2][8];
    #pragma unroll
    for (int i = 0; i < 2; i++)
        #pragma unroll
        for (int j = 0; j < 8; j++) acc[i][j] = make_float4(0.f, 0.f, 0.f, 0.f);

    const unsigned aoff = (unsigned)(wm * 32 + (lane & 15)) * PITCH + ((lane & 16) ? 16u : 0u);
    const unsigned boff = (unsigned)(wn * 64 + (lane & 7) + ((lane & 16) ? 8 : 0)) * PITCH
                        + ((lane & 8) ? 16u : 0u);

    const int nch = K >> 5;
    issue(0, 0);
    for (int c = 0; c < nch; c++) {
        const int b = c & 1;
        if (c + 1 < nch) { issue(b ^ 1, c + 1); CPA_WAIT1(); }
        else             { CPA_WAIT0(); }
        __syncthreads();

        const unsigned uah = us + b * (4 * APL);
        const unsigned ual = uah + APL;
        const unsigned ubh = uah + 2 * APL;
        const unsigned ubl = uah + 3 * APL;

        #pragma unroll
        for (int ks = 0; ks < 2; ks++) {
            const unsigned kb = ks * 32;
            unsigned ah[2][4], al[2][4];
            #pragma unroll
            for (int mt = 0; mt < 2; mt++) {
                unsigned ao = aoff + mt * 16 * PITCH + kb;
                ldm4(uah + ao, ah[mt][0], ah[mt][1], ah[mt][2], ah[mt][3]);
                ldm4(ual + ao, al[mt][0], al[mt][1], al[mt][2], al[mt][3]);
            }
            #pragma unroll
            for (int np = 0; np < 4; np++) {
                unsigned bo = boff + np * 16 * PITCH + kb;
                unsigned bh[4], bl[4];
                ldm4(ubh + bo, bh[0], bh[1], bh[2], bh[3]);
                ldm4(ubl + bo, bl[0], bl[1], bl[2], bl[3]);
                #pragma unroll
                for (int mt = 0; mt < 2; mt++) {
                    hmma(acc[mt][2*np  ], ah[mt][0], ah[mt][1], ah[mt][2], ah[mt][3], bh[0], bh[1]);
                    hmma(acc[mt][2*np+1], ah[mt][0], ah[mt][1], ah[mt][2], ah[mt][3], bh[2], bh[3]);
                    hmma(acc[mt][2*np  ], ah[mt][0], ah[mt][1], ah[mt][2], ah[mt][3], bl[0], bl[1]);
                    hmma(acc[mt][2*np+1], ah[mt][0], ah[mt][1], ah[mt][2], ah[mt][3], bl[2], bl[3]);
                    hmma(acc[mt][2*np  ], al[mt][0], al[mt][1], al[mt][2], al[mt][3], bh[0], bh[1]);
                    hmma(acc[mt][2*np+1], al[mt][0], al[mt][1], al[mt][2], al[mt][3], bh[2], bh[3]);
                }
            }
        }
        __syncthreads();
    }

    const int qr = lane >> 2;
    const int qc = (lane & 3) << 1;
    #pragma unroll
    for (int mt = 0; mt < 2; mt++) {
        #pragma unroll
        for (int nt = 0; nt < 8; nt++) {
            int col = bn + wn * 64 + nt * 8 + qc;
            float2 bb = make_float2(0.f, 0.f);
            if (EPI != EPI_NONE) bb = *(const float2*)&bias[col];
            #pragma unroll
            for (int half = 0; half < 2; half++) {
                int row = bm + wm * 32 + mt * 16 + qr + half * 8;
                float2 v;
                v.x = half ? acc[mt][nt].z : acc[mt][nt].x;
                v.y = half ? acc[mt][nt].w : acc[mt][nt].y;
                if (EPI != EPI_NONE) { v.x += bb.x; v.y += bb.y; }
                if (EPI == EPI_BIAS_GELU) { v.x = gelu_tanh(v.x); v.y = gelu_tanh(v.y); }
                if (EPI == EPI_BIAS_RES) {
                    float2 rr = *(const float2*)&res[(size_t)row * ldres + col];
                    v.x += rr.x; v.y += rr.y;
                }
                if (OBF) {
                    v.x *= scale; v.y *= scale;
                    unsigned h, l; cvt2(v.x, v.y, h, l);
                    *(unsigned*)(Ch + (size_t)row * ldc + col) = h;
                    *(unsigned*)(Cl + (size_t)row * ldc + col) = l;
                } else {
                    *(float2*)&C[(size_t)row * ldc + col] = v;
                }
            }
        }
    }
}

// ================= fused flash attention (bf16 in/out, cp.async KV) =================
#define FPITCH 144
#define QPL (128 * FPITCH)      // 18432
#define KVPL (64 * FPITCH)      // 9216
#define FLASH_SMEM (2 * QPL + 8 * KVPL)   // 110592

__global__ __launch_bounds__(256, 2)
void flash_k()
{
    extern __shared__ char sm[];
    const unsigned uq  = sm2u(sm);                 // qh, ql
    const unsigned ukv = uq + 2 * QPL;             // 2 buffers x 4 planes

    const int tid  = threadIdx.x;
    const int lane = tid & 31;
    const int wid  = tid >> 5;
    const int h    = blockIdx.y;
    const int bq   = blockIdx.x * 128;
    const int hc   = h * D_HEAD;

    auto issue = [&](int b, int kb) {
        const unsigned sb = ukv + b * (4 * KVPL);
        #pragma unroll
        for (int i = tid; i < 512; i += 256) {
            int r = i >> 3, cc = i & 7;
            unsigned so = r * FPITCH + cc * 16;
            size_t go = (size_t)(kb + r) * D_MODEL + hc + cc * 8;
            CPA16(sb + 0*KVPL + so, g_kh + go);
            CPA16(sb + 1*KVPL + so, g_kl + go);
            CPA16(sb + 2*KVPL + so, g_vh + go);
            CPA16(sb + 3*KVPL + so, g_vl + go);
        }
        CPA_COMMIT();
    };

    issue(0, 0);
    // Q tile copy (pre-scaled bf16 hi/lo)
    for (int i = tid; i < 1024; i += 256) {
        int r = i >> 3, cc = i & 7;
        size_t go = (size_t)(bq + r) * D_MODEL + hc + cc * 8;
        unsigned so = r * FPITCH + cc * 16;
        *(uint4*)(sm + so)       = *(const uint4*)(g_qh + go);
        *(uint4*)(sm + QPL + so) = *(const uint4*)(g_ql + go);
    }

    const unsigned aoff = (unsigned)(wid * 16 + (lane & 15)) * FPITCH + ((lane & 16) ? 16u : 0u);
    const unsigned boff = (unsigned)((lane & 7) + ((lane & 16) ? 8 : 0)) * FPITCH
                        + ((lane & 8) ? 16u : 0u);
    const unsigned voff = (unsigned)((lane & 7) + ((lane & 8) ? 8 : 0)) * FPITCH
                        + ((lane & 16) ? 16u : 0u);

    float4 oacc[8];
    #pragma unroll
    for (int t = 0; t < 8; t++) oacc[t] = make_float4(0.f, 0.f, 0.f, 0.f);
    float m0 = -1e30f, m1 = -1e30f, l0 = 0.f, l1 = 0.f;

    const int NITER = N_NODES / 64;
    for (int c = 0; c < NITER; c++) {
        const int b = c & 1;
        if (c + 1 < NITER) { issue(b ^ 1, (c + 1) * 64); CPA_WAIT1(); }
        else               { CPA_WAIT0(); }
        __syncthreads();

        const unsigned ukh = ukv + b * (4 * KVPL);
        const unsigned ukl = ukh + KVPL;
        const unsigned uvh = ukh + 2 * KVPL;
        const unsigned uvl = ukh + 3 * KVPL;

        // ---- S = Q K^T ----
        float4 sacc[8];
        #pragma unroll
        for (int t = 0; t < 8; t++) sacc[t] = make_float4(0.f, 0.f, 0.f, 0.f);
        #pragma unroll
        for (int t = 0; t < 4; t++) {
            unsigned ao = aoff + t * 32;
            unsigned ah[4], al[4];
            ldm4(uq + ao, ah[0], ah[1], ah[2], ah[3]);
            ldm4(uq + QPL + ao, al[0], al[1], al[2], al[3]);
            #pragma unroll
            for (int ng = 0; ng < 4; ng++) {
                unsigned bo = boff + ng * (16 * FPITCH) + t * 32;
                unsigned bh[4], bl[4];
                ldm4(ukh + bo, bh[0], bh[1], bh[2], bh[3]);
                ldm4(ukl + bo, bl[0], bl[1], bl[2], bl[3]);
                hmma(sacc[2*ng  ], ah[0], ah[1], ah[2], ah[3], bh[0], bh[1]);
                hmma(sacc[2*ng+1], ah[0], ah[1], ah[2], ah[3], bh[2], bh[3]);
                hmma(sacc[2*ng  ], ah[0], ah[1], ah[2], ah[3], bl[0], bl[1]);
                hmma(sacc[2*ng+1], ah[0], ah[1], ah[2], ah[3], bl[2], bl[3]);
                hmma(sacc[2*ng  ], al[0], al[1], al[2], al[3], bh[0], bh[1]);
                hmma(sacc[2*ng+1], al[0], al[1], al[2], al[3], bh[2], bh[3]);
            }
        }

        // ---- online softmax ----
        float mx0 = -1e30f, mx1 = -1e30f;
        #pragma unroll
        for (int t = 0; t < 8; t++) {
            mx0 = fmaxf(mx0, fmaxf(sacc[t].x, sacc[t].y));
            mx1 = fmaxf(mx1, fmaxf(sacc[t].z, sacc[t].w));
        }
        mx0 = fmaxf(mx0, __shfl_xor_sync(0xffffffffu, mx0, 1));
        mx0 = fmaxf(mx0, __shfl_xor_sync(0xffffffffu, mx0, 2));
        mx1 = fmaxf(mx1, __shfl_xor_sync(0xffffffffu, mx1, 1));
        mx1 = fmaxf(mx1, __shfl_xor_sync(0xffffffffu, mx1, 2));
        float mn0 = fmaxf(m0, mx0), mn1 = fmaxf(m1, mx1);
        float c0 = __expf(m0 - mn0), c1 = __expf(m1 - mn1);
        m0 = mn0; m1 = mn1;

        unsigned pxyh[8], pxyl[8], pzwh[8], pzwl[8];
        float s0 = 0.f, s1 = 0.f;
        #pragma unroll
        for (int t = 0; t < 8; t++) {
            float ex = __expf(sacc[t].x - mn0);
            float ey = __expf(sacc[t].y - mn0);
            float ez = __expf(sacc[t].z - mn1);
            float ew = __expf(sacc[t].w - mn1);
            s0 += ex + ey; s1 += ez + ew;
            cvt2(ex, ey, pxyh[t], pxyl[t]);
            cvt2(ez, ew, pzwh[t], pzwl[t]);
        }
        s0 += __shfl_xor_sync(0xffffffffu, s0, 1);
        s0 += __shfl_xor_sync(0xffffffffu, s0, 2);
        s1 += __shfl_xor_sync(0xffffffffu, s1, 1);
        s1 += __shfl_xor_sync(0xffffffffu, s1, 2);
        l0 = l0 * c0 + s0;
        l1 = l1 * c1 + s1;
        #pragma unroll
        for (int t = 0; t < 8; t++) {
            oacc[t].x *= c0; oacc[t].y *= c0;
            oacc[t].z *= c1; oacc[t].w *= c1;
        }

        // ---- O += P V ----
        #pragma unroll
        for (int t = 0; t < 4; t++) {
            unsigned ah[4] = { pxyh[2*t], pzwh[2*t], pxyh[2*t+1], pzwh[2*t+1] };
            unsigned al[4] = { pxyl[2*t], pzwl[2*t], pxyl[2*t+1], pzwl[2*t+1] };
            #pragma unroll
            for (int ng = 0; ng < 4; ng++) {
                unsigned vo = voff + t * (16 * FPITCH) + ng * 32;
                unsigned bh[4], bl[4];
                ldm4t(uvh + vo, bh[0], bh[1], bh[2], bh[3]);
                ldm4t(uvl + vo, bl[0], bl[1], bl[2], bl[3]);
                hmma(oacc[2*ng  ], ah[0], ah[1], ah[2], ah[3], bh[0], bh[1]);
                hmma(oacc[2*ng+1], ah[0], ah[1], ah[2], ah[3], bh[2], bh[3]);
                hmma(oacc[2*ng  ], ah[0], ah[1], ah[2], ah[3], bl[0], bl[1]);
                hmma(oacc[2*ng+1], ah[0], ah[1], ah[2], ah[3], bl[2], bl[3]);
                hmma(oacc[2*ng  ], al[0], al[1], al[2], al[3], bh[0], bh[1]);
                hmma(oacc[2*ng+1], al[0], al[1], al[2], al[3], bh[2], bh[3]);
            }
        }
        __syncthreads();
    }

    // ---- epilogue: write O as bf16 hi/lo ----
    const int qr = lane >> 2;
    const int qc = (lane & 3) << 1;
    float inv0 = 1.0f / l0, inv1 = 1.0f / l1;
    int r0 = bq + wid * 16 + qr;
    int r1 = r0 + 8;
    #pragma unroll
    for (int t = 0; t < 8; t++) {
        int col = hc + t * 8 + qc;
        unsigned hh, ll;
        cvt2(oacc[t].x * inv0, oacc[t].y * inv0, hh, ll);
        *(unsigned*)(g_oh + (size_t)r0 * D_MODEL + col) = hh;
        *(unsigned*)(g_ol + (size_t)r0 * D_MODEL + col) = ll;
        cvt2(oacc[t].z * inv1, oacc[t].w * inv1, hh, ll);
        *(unsigned*)(g_oh + (size_t)r1 * D_MODEL + col) = hh;
        *(unsigned*)(g_ol + (size_t)r1 * D_MODEL + col) = ll;
    }
}

// ---------------- LayerNorm -> bf16 hi/lo ----------------
__global__ void ln_k(const float* __restrict__ x, const float* __restrict__ s,
                     const float* __restrict__ b, bf16* __restrict__ yh,
                     bf16* __restrict__ yl)
{
    const int row = blockIdx.x;
    const int tid = threadIdx.x;   // 256
    const float* xr = x + (size_t)row * D_MODEL;

    float2 xv = *(const float2*)&xr[2 * tid];
    float sum = xv.x + xv.y;
    float sq  = xv.x * xv.x + xv.y * xv.y;

#pragma unroll
    for (int off = 16; off > 0; off >>= 1) {
        sum += __shfl_xor_sync(0xffffffffu, sum, off);
        sq  += __shfl_xor_sync(0xffffffffu, sq,  off);
    }
    __shared__ float rs[8], rq[8];
    __shared__ float s_mean, s_inv;
    if ((tid & 31) == 0) { rs[tid >> 5] = sum; rq[tid >> 5] = sq; }
    __syncthreads();
    if (tid == 0) {
        float ts = 0.f, tq = 0.f;
#pragma unroll
        for (int i = 0; i < 8; i++) { ts += rs[i]; tq += rq[i]; }
        float mean = ts * (1.0f / D_MODEL);
        float var  = tq * (1.0f / D_MODEL) - mean * mean;
        s_mean = mean;
        s_inv  = rsqrtf(var + 1e-5f);
    }
    __syncthreads();
    float mean = s_mean, inv = s_inv;
    float2 sv = *(const float2*)&s[2 * tid];
    float2 bv = *(const float2*)&b[2 * tid];
    float v0 = (xv.x - mean) * inv * sv.x + bv.x;
    float v1 = (xv.y - mean) * inv * sv.y + bv.y;
    unsigned h, l; cvt2(v0, v1, h, l);
    *(unsigned*)(yh + (size_t)row * D_MODEL + 2 * tid) = h;
    *(unsigned*)(yl + (size_t)row * D_MODEL + 2 * tid) = l;
}

// ---------------- GCN kernels ----------------
__global__ void deg_init_k() {
    int i = blockIdx.x * blockDim.x + threadIdx.x;
    if (i < N_NODES) g_dinv[i] = 1.0f;
}
__global__ void deg_acc_k(const int* __restrict__ ei, const float* __restrict__ ew) {
    int e = blockIdx.x * blockDim.x + threadIdx.x;
    if (e < N_EDGES) atomicAdd(&g_dinv[ei[N_EDGES + e]], ew[e]);
}
__global__ void deg_fin_k() {
    int i = blockIdx.x * blockDim.x + threadIdx.x;
    if (i < N_NODES) g_dinv[i] = rsqrtf(g_dinv[i]);
}
__global__ void mp_init_k(const float* __restrict__ bg) {
    int idx = blockIdx.x * blockDim.x + threadIdx.x;
    int n  = idx >> 7;
    int d4 = (idx & 127) << 2;
    float di = g_dinv[n];
    float c  = di * di;
    float4 xv = *(const float4*)&g_xt[(size_t)n * D_MODEL + d4];
    float4 bb = *(const float4*)&bg[d4];
    float4 r;
    r.x = fmaf(xv.x, c, bb.x); r.y = fmaf(xv.y, c, bb.y);
    r.z = fmaf(xv.z, c, bb.z); r.w = fmaf(xv.w, c, bb.w);
    *(float4*)&g_mp[(size_t)n * D_MODEL + d4] = r;
}
__global__ void scatter_k(const int* __restrict__ ei, const float* __restrict__ ew) {
    int idx = blockIdx.x * blockDim.x + threadIdx.x;
    int e  = idx >> 7;
    int d4 = (idx & 127) << 2;
    int s  = ei[e];
    int t  = ei[N_EDGES + e];
    float coef = g_dinv[s] * ew[e] * g_dinv[t];
    float4 xv = *(const float4*)&g_xt[(size_t)s * D_MODEL + d4];
    float* dstp = &g_mp[(size_t)t * D_MODEL + d4];
    atomicAdd(dstp + 0, xv.x * coef);
    atomicAdd(dstp + 1, xv.y * coef);
    atomicAdd(dstp + 2, xv.z * coef);
    atomicAdd(dstp + 3, xv.w * coef);
}

// ---------------- concat [mp | tf] -> cat bf16 hi/lo [N, 1024] ----------------
__global__ void concat_k() {
    int idx = blockIdx.x * blockDim.x + threadIdx.x;
    int n  = idx >> 7;
    int d4 = (idx & 127) << 2;
    float4 a = *(const float4*)&g_mp[(size_t)n * D_MODEL + d4];
    float4 b = *(const float4*)&g_tf[(size_t)n * D_MODEL + d4];
    uint2 h, l;
    cvt4(a.x, a.y, a.z, a.w, h, l);
    *(uint2*)(g_cth + (size_t)n * 1024 + d4) = h;
    *(uint2*)(g_ctl + (size_t)n * 1024 + d4) = l;
    cvt4(b.x, b.y, b.z, b.w, h, l);
    *(uint2*)(g_cth + (size_t)n * 1024 + 512 + d4) = h;
    *(uint2*)(g_ctl + (size_t)n * 1024 + 512 + d4) = l;
}

// ---------------- launch ----------------
extern "C" void kernel_launch(void* const* d_in, const int* in_sizes, int n_in,
                              void* d_out, int out_size)
{
    (void)in_sizes; (void)n_in; (void)out_size;
    const float* x     = (const float*)d_in[0];
    const int*   ei    = (const int*)  d_in[1];
    const float* ew    = (const float*)d_in[2];
    const float* Wg    = (const float*)d_in[3];
    const float* bg    = (const float*)d_in[4];
    const float* ln1_s = (const float*)d_in[5];
    const float* ln1_b = (const float*)d_in[6];
    const float* Wq    = (const float*)d_in[7];
    const float* bq    = (const float*)d_in[8];
    const float* Wk    = (const float*)d_in[9];
    const float* bk    = (const float*)d_in[10];
    const float* Wv    = (const float*)d_in[11];
    const float* bv    = (const float*)d_in[12];
    const float* Wo    = (const float*)d_in[13];
    const float* bo    = (const float*)d_in[14];
    const float* ln2_s = (const float*)d_in[15];
    const float* ln2_b = (const float*)d_in[16];
    const float* W1    = (const float*)d_in[17];
    const float* b1    = (const float*)d_in[18];
    const float* W2    = (const float*)d_in[19];
    const float* b2    = (const float*)d_in[20];
    const float* Wa    = (const float*)d_in[21];
    const float* ba    = (const float*)d_in[22];
    float* out = (float*)d_out;

    float *xt, *mp, *x1, *tf;
    cudaGetSymbolAddress((void**)&xt, g_xt);
    cudaGetSymbolAddress((void**)&mp, g_mp);
    cudaGetSymbolAddress((void**)&x1, g_x1);
    cudaGetSymbolAddress((void**)&tf, g_tf);

#define SYM(p, g) bf16* p; cudaGetSymbolAddress((void**)&p, g)
    SYM(xbh, g_xbh); SYM(xbl, g_xbl);
    SYM(hh,  g_hh);  SYM(hl,  g_hl);
    SYM(qh,  g_qh);  SYM(ql,  g_ql);
    SYM(kh,  g_kh);  SYM(kl,  g_kl);
    SYM(vh,  g_vh);  SYM(vl,  g_vl);
    SYM(oh,  g_oh);  SYM(ol,  g_ol);
    SYM(h2h, g_h2h); SYM(h2l, g_h2l);
    SYM(m1h, g_m1h); SYM(m1l, g_m1l);
    SYM(cth, g_cth); SYM(ctl, g_ctl);
    SYM(Wgh, g_Wgh); SYM(Wgl, g_Wgl);
    SYM(Wqh, g_Wqh); SYM(Wql, g_Wql);
    SYM(Wkh, g_Wkh); SYM(Wkl, g_Wkl);
    SYM(Wvh, g_Wvh); SYM(Wvl, g_Wvl);
    SYM(Woh, g_Woh); SYM(Wol, g_Wol);
    SYM(W1h, g_W1h); SYM(W1l, g_W1l);
    SYM(W2h, g_W2h); SYM(W2l, g_W2l);
    SYM(Wah, g_Wah); SYM(Wal, g_Wal);
#undef SYM

    const int GSMEM = 2 * 4 * (128 * PITCH);   // 81920
    cudaFuncSetAttribute(tgemm2_k<EPI_NONE,      false>, cudaFuncAttributeMaxDynamicSharedMemorySize, GSMEM);
    cudaFuncSetAttribute(tgemm2_k<EPI_BIAS,      true >, cudaFuncAttributeMaxDynamicSharedMemorySize, GSMEM);
    cudaFuncSetAttribute(tgemm2_k<EPI_BIAS_GELU, true >, cudaFuncAttributeMaxDynamicSharedMemorySize, GSMEM);
    cudaFuncSetAttribute(tgemm2_k<EPI_BIAS_RES,  false>, cudaFuncAttributeMaxDynamicSharedMemorySize, GSMEM);
    cudaFuncSetAttribute(flash_k, cudaFuncAttributeMaxDynamicSharedMemorySize, FLASH_SMEM);

    dim3 wb(32, 8);
    // ---- weight + input prep ----
    wprep_k<<<dim3(16, 16), wb>>>(Wg, Wgh, Wgl, D_MODEL, D_MODEL);
    wprep_k<<<dim3(16, 16), wb>>>(Wq, Wqh, Wql, D_MODEL, D_MODEL);
    wprep_k<<<dim3(16, 16), wb>>>(Wk, Wkh, Wkl, D_MODEL, D_MODEL);
    wprep_k<<<dim3(16, 16), wb>>>(Wv, Wvh, Wvl, D_MODEL, D_MODEL);
    wprep_k<<<dim3(16, 16), wb>>>(Wo, Woh, Wol, D_MODEL, D_MODEL);
    wprep_k<<<dim3(64, 16), wb>>>(W1, W1h, W1l, D_MODEL, D_FF);
    wprep_k<<<dim3(16, 64), wb>>>(W2, W2h, W2l, D_FF, D_MODEL);
    wprep_k<<<dim3(16, 32), wb>>>(Wa, Wah, Wal, 2 * D_MODEL, D_MODEL);
    aprep_k<<<(N_NODES * D_MODEL / 4) / 256, 256>>>(x, xbh, xbl);

    dim3 g512(4, 32), gff(16, 32);

    // ---- GCN branch ----
    tgemm2_k<EPI_NONE, false><<<g512, 256, GSMEM>>>(
        xbh, xbl, D_MODEL, Wgh, Wgl, xt, nullptr, nullptr, D_MODEL,
        nullptr, nullptr, 0, D_MODEL, 1.0f);
    deg_init_k<<<N_NODES / 256, 256>>>();
    deg_acc_k<<<N_EDGES / 256, 256>>>(ei, ew);
    deg_fin_k<<<N_NODES / 256, 256>>>();
    mp_init_k<<<(N_NODES * D_MODEL / 4) / 256, 256>>>(bg);
    scatter_k<<<(N_EDGES * (D_MODEL / 4)) / 256, 256>>>(ei, ew);

    // ---- Transformer branch ----
    ln_k<<<N_NODES, 256>>>(x, ln1_s, ln1_b, hh, hl);
    tgemm2_k<EPI_BIAS, true><<<g512, 256, GSMEM>>>(
        hh, hl, D_MODEL, Wqh, Wql, nullptr, qh, ql, D_MODEL,
        bq, nullptr, 0, D_MODEL, 0.125f);
    tgemm2_k<EPI_BIAS, true><<<g512, 256, GSMEM>>>(
        hh, hl, D_MODEL, Wkh, Wkl, nullptr, kh, kl, D_MODEL,
        bk, nullptr, 0, D_MODEL, 1.0f);
    tgemm2_k<EPI_BIAS, true><<<g512, 256, GSMEM>>>(
        hh, hl, D_MODEL, Wvh, Wvl, nullptr, vh, vl, D_MODEL,
        bv, nullptr, 0, D_MODEL, 1.0f);

    flash_k<<<dim3(N_NODES / 128, N_HEADS), 256, FLASH_SMEM>>>();

    tgemm2_k<EPI_BIAS_RES, false><<<g512, 256, GSMEM>>>(
        oh, ol, D_MODEL, Woh, Wol, x1, nullptr, nullptr, D_MODEL,
        bo, x, D_MODEL, D_MODEL, 1.0f);
    ln_k<<<N_NODES, 256>>>(x1, ln2_s, ln2_b, h2h, h2l);
    tgemm2_k<EPI_BIAS_GELU, true><<<gff, 256, GSMEM>>>(
        h2h, h2l, D_MODEL, W1h, W1l, nullptr, m1h, m1l, D_FF,
        b1, nullptr, 0, D_MODEL, 1.0f);
    tgemm2_k<EPI_BIAS_RES, false><<<g512, 256, GSMEM>>>(
        m1h, m1l, D_FF, W2h, W2l, tf, nullptr, nullptr, D_MODEL,
        b2, x1, D_MODEL, D_FF, 1.0f);

    // ---- merge ----
    concat_k<<<(N_NODES * D_MODEL / 4) / 256, 256>>>();
    tgemm2_k<EPI_BIAS_RES, false><<<g512, 256, GSMEM>>>(
        cth, ctl, 2 * D_MODEL, Wah, Wal, out, nullptr, nullptr, D_MODEL,
        ba, x, D_MODEL, 2 * D_MODEL, 1.0f);
}

// round 11
// speedup vs baseline: 6.1209x; 1.2584x over previous
#include <cuda_runtime.h>
#include <cuda_bf16.h>
#include <math.h>

#define N_NODES 4096
#define D_MODEL 512
#define N_HEADS 8
#define D_HEAD  64
#define D_FF    2048
#define N_EDGES 65536

#define EPI_NONE      0
#define EPI_BIAS      1
#define EPI_BIAS_GELU 2
#define EPI_BIAS_RES  3

#define PITCH 80   // GEMM smem pitch: 32 bf16 (64B) + 16B pad
typedef __nv_bfloat16 bf16;

// ---------------- fp32 scratch ----------------
__device__ float g_xt [N_NODES * D_MODEL];
__device__ float g_mp [N_NODES * D_MODEL];
__device__ float g_dinv[N_NODES];
__device__ float g_x1 [N_NODES * D_MODEL];
__device__ float g_tf [N_NODES * D_MODEL];

// ---------------- bf16 activations (hi plane; lo only where split needed) ----
__device__ bf16 g_xbh[N_NODES * D_MODEL],  g_xbl[N_NODES * D_MODEL];
__device__ bf16 g_hh [N_NODES * D_MODEL],  g_hl [N_NODES * D_MODEL];
__device__ bf16 g_qh [N_NODES * D_MODEL];
__device__ bf16 g_kh [N_NODES * D_MODEL];
__device__ bf16 g_vh [N_NODES * D_MODEL];
__device__ bf16 g_oh [N_NODES * D_MODEL],  g_ol [N_NODES * D_MODEL];
__device__ bf16 g_h2h[N_NODES * D_MODEL],  g_h2l[N_NODES * D_MODEL];
__device__ bf16 g_m1h[N_NODES * D_FF],     g_m1l[N_NODES * D_FF];
__device__ bf16 g_cth[N_NODES * 2*D_MODEL],g_ctl[N_NODES * 2*D_MODEL];

// ---------------- bf16 hi/lo transposed weights [N,K] ----------------
__device__ bf16 g_Wgh[D_MODEL*D_MODEL],  g_Wgl[D_MODEL*D_MODEL];
__device__ bf16 g_Wqh[D_MODEL*D_MODEL],  g_Wql[D_MODEL*D_MODEL];
__device__ bf16 g_Wkh[D_MODEL*D_MODEL],  g_Wkl[D_MODEL*D_MODEL];
__device__ bf16 g_Wvh[D_MODEL*D_MODEL],  g_Wvl[D_MODEL*D_MODEL];
__device__ bf16 g_Woh[D_MODEL*D_MODEL],  g_Wol[D_MODEL*D_MODEL];
__device__ bf16 g_W1h[D_MODEL*D_FF],     g_W1l[D_MODEL*D_FF];
__device__ bf16 g_W2h[D_FF*D_MODEL],     g_W2l[D_FF*D_MODEL];
__device__ bf16 g_Wah[2*D_MODEL*D_MODEL],g_Wal[2*D_MODEL*D_MODEL];

// ---------------- helpers ----------------
__device__ __forceinline__ float gelu_tanh(float x) {
    float x3 = x * x * x;
    float t  = tanhf(0.7978845608028654f * (x + 0.044715f * x3));
    return 0.5f * x * (1.0f + t);
}
__device__ __forceinline__ unsigned sm2u(const void* p) {
    unsigned a;
    asm("{ .reg .u64 t; cvta.to.shared.u64 t, %1; cvt.u32.u64 %0, t; }" : "=r"(a) : "l"(p));
    return a;
}
__device__ __forceinline__ void ldm4(unsigned addr, unsigned& r0, unsigned& r1,
                                     unsigned& r2, unsigned& r3) {
    asm volatile("ldmatrix.sync.aligned.m8n8.x4.shared.b16 {%0,%1,%2,%3}, [%4];"
                 : "=r"(r0), "=r"(r1), "=r"(r2), "=r"(r3) : "r"(addr));
}
__device__ __forceinline__ void ldm4t(unsigned addr, unsigned& r0, unsigned& r1,
                                      unsigned& r2, unsigned& r3) {
    asm volatile("ldmatrix.sync.aligned.m8n8.x4.trans.shared.b16 {%0,%1,%2,%3}, [%4];"
                 : "=r"(r0), "=r"(r1), "=r"(r2), "=r"(r3) : "r"(addr));
}
__device__ __forceinline__ void hmma(float4& d, unsigned a0, unsigned a1,
                                     unsigned a2, unsigned a3,
                                     unsigned b0, unsigned b1) {
    asm volatile("mma.sync.aligned.m16n8k16.row.col.f32.bf16.bf16.f32 "
                 "{%0,%1,%2,%3}, {%4,%5,%6,%7}, {%8,%9}, {%0,%1,%2,%3};"
                 : "+f"(d.x), "+f"(d.y), "+f"(d.z), "+f"(d.w)
                 : "r"(a0), "r"(a1), "r"(a2), "r"(a3), "r"(b0), "r"(b1));
}
__device__ __forceinline__ void cvt4(float x0, float x1, float x2, float x3,
                                     uint2& hi, uint2& lo) {
    bf16 h0 = __float2bfloat16(x0), h1 = __float2bfloat16(x1);
    bf16 h2 = __float2bfloat16(x2), h3 = __float2bfloat16(x3);
    bf16 l0 = __float2bfloat16(x0 - __bfloat162float(h0));
    bf16 l1 = __float2bfloat16(x1 - __bfloat162float(h1));
    bf16 l2 = __float2bfloat16(x2 - __bfloat162float(h2));
    bf16 l3 = __float2bfloat16(x3 - __bfloat162float(h3));
    hi.x = ((unsigned)__bfloat16_as_ushort(h1) << 16) | __bfloat16_as_ushort(h0);
    hi.y = ((unsigned)__bfloat16_as_ushort(h3) << 16) | __bfloat16_as_ushort(h2);
    lo.x = ((unsigned)__bfloat16_as_ushort(l1) << 16) | __bfloat16_as_ushort(l0);
    lo.y = ((unsigned)__bfloat16_as_ushort(l3) << 16) | __bfloat16_as_ushort(l2);
}
__device__ __forceinline__ void cvt2(float x, float y, unsigned& hi, unsigned& lo) {
    bf16 hx = __float2bfloat16(x), hy = __float2bfloat16(y);
    bf16 lx = __float2bfloat16(x - __bfloat162float(hx));
    bf16 ly = __float2bfloat16(y - __bfloat162float(hy));
    hi = ((unsigned)__bfloat16_as_ushort(hy) << 16) | __bfloat16_as_ushort(hx);
    lo = ((unsigned)__bfloat16_as_ushort(ly) << 16) | __bfloat16_as_ushort(lx);
}
// pack {lo=x, hi=y} into one bf16x2 register
__device__ __forceinline__ unsigned pack2(float x, float y) {
    unsigned r;
    asm("cvt.rn.bf16x2.f32 %0, %1, %2;" : "=r"(r) : "f"(y), "f"(x));
    return r;
}

#define CPA16(s, g)  asm volatile("cp.async.cg.shared.global [%0], [%1], 16;" :: "r"(s), "l"(g))
#define CPA_COMMIT() asm volatile("cp.async.commit_group;" ::: "memory")
#define CPA_WAIT1()  asm volatile("cp.async.wait_group 1;" ::: "memory")
#define CPA_WAIT0()  asm volatile("cp.async.wait_group 0;" ::: "memory")

// ================= prep kernels =================
struct WSeg { const float* W; bf16* hi; bf16* lo; int K; int N; };
struct WArgs { WSeg s[8]; };

// fused: 8x fp32 [K,N] -> transposed bf16 hi/lo [N,K]
__global__ void wprep8_k(WArgs a)
{
    __shared__ float t[32][33];
    WSeg p = a.s[blockIdx.z];
    int k0 = blockIdx.y * 32, n0 = blockIdx.x * 32;
    if (k0 >= p.K || n0 >= p.N) return;
    int tx = threadIdx.x, ty = threadIdx.y;   // 32 x 8
    #pragma unroll
    for (int i = 0; i < 4; i++)
        t[ty + 8*i][tx] = p.W[(size_t)(k0 + ty + 8*i) * p.N + n0 + tx];
    __syncthreads();
    #pragma unroll
    for (int i = 0; i < 4; i++) {
        float v = t[tx][ty + 8*i];
        bf16 h = __float2bfloat16(v);
        bf16 l = __float2bfloat16(v - __bfloat162float(h));
        size_t o = (size_t)(n0 + ty + 8*i) * p.K + k0 + tx;
        p.hi[o] = h; p.lo[o] = l;
    }
}
// fp32 -> bf16 hi/lo elementwise; also initializes dinv
__global__ void aprep_k(const float* __restrict__ x, bf16* __restrict__ hi,
                        bf16* __restrict__ lo)
{
    int idx = blockIdx.x * blockDim.x + threadIdx.x;
    if (idx < N_NODES) g_dinv[idx] = 1.0f;
    float4 v = *(const float4*)(x + idx * 4);
    uint2 h, l; cvt4(v.x, v.y, v.z, v.w, h, l);
    *(uint2*)(hi + idx * 4) = h;
    *(uint2*)(lo + idx * 4) = l;
}

// ================= cp.async double-buffered HMMA split-bf16 GEMM =================
// OBF: 0 = fp32 out, 1 = bf16 hi only, 2 = bf16 hi+lo
template<int EPI, int OBF>
__global__ __launch_bounds__(256)
void tgemm2_k(const bf16* __restrict__ Ah, const bf16* __restrict__ Al, int lda,
              const bf16* __restrict__ Bh, const bf16* __restrict__ Bl,
              float* __restrict__ C, bf16* __restrict__ Ch, bf16* __restrict__ Cl,
              int ldc, const float* __restrict__ bias,
              const float* __restrict__ res, int ldres, int K, float scale)
{
    extern __shared__ char smem[];
    const int tid  = threadIdx.x;
    const int lane = tid & 31;
    const int wid  = tid >> 5;
    const int wm   = wid & 3;
    const int wn   = wid >> 2;
    const int bm   = blockIdx.y * 128;
    const int bn   = blockIdx.x * 128;

    constexpr int APL = 128 * PITCH;   // 10240 bytes per plane
    const unsigned us = sm2u(smem);

    const bf16* g0 = Ah + (size_t)bm * lda;
    const bf16* g1 = Al + (size_t)bm * lda;
    const bf16* g2 = Bh + (size_t)bn * K;
    const bf16* g3 = Bl + (size_t)bn * K;

    auto issue = [&](int b, int c) {
        const int k0 = c * 32;
        const unsigned sb = us + b * (4 * APL);
        #pragma unroll
        for (int i = tid; i < 512; i += 256) {
            int r = i >> 2, cc = i & 3;
            unsigned so = r * PITCH + cc * 16;
            size_t goA = (size_t)r * lda + k0 + cc * 8;
            size_t goB = (size_t)r * K   + k0 + cc * 8;
            CPA16(sb + 0*APL + so, g0 + goA);
            CPA16(sb + 1*APL + so, g1 + goA);
            CPA16(sb + 2*APL + so, g2 + goB);
            CPA16(sb + 3*APL + so, g3 + goB);
        }
        CPA_COMMIT();
    };

    float4 acc[2][8];
    #pragma unroll
    for (int i = 0; i < 2; i++)
        #pragma unroll
        for (int j = 0; j < 8; j++) acc[i][j] = make_float4(0.f, 0.f, 0.f, 0.f);

    const unsigned aoff = (unsigned)(wm * 32 + (lane & 15)) * PITCH + ((lane & 16) ? 16u : 0u);
    const unsigned boff = (unsigned)(wn * 64 + (lane & 7) + ((lane & 16) ? 8 : 0)) * PITCH
                        + ((lane & 8) ? 16u : 0u);

    const int nch = K >> 5;
    issue(0, 0);
    for (int c = 0; c < nch; c++) {
        const int b = c & 1;
        if (c + 1 < nch) { issue(b ^ 1, c + 1); CPA_WAIT1(); }
        else             { CPA_WAIT0(); }
        __syncthreads();

        const unsigned uah = us + b * (4 * APL);
        const unsigned ual = uah + APL;
        const unsigned ubh = uah + 2 * APL;
        const unsigned ubl = uah + 3 * APL;

        #pragma unroll
        for (int ks = 0; ks < 2; ks++) {
            const unsigned kb = ks * 32;
            unsigned ah[2][4], al[2][4];
            #pragma unroll
            for (int mt = 0; mt < 2; mt++) {
                unsigned ao = aoff + mt * 16 * PITCH + kb;
                ldm4(uah + ao, ah[mt][0], ah[mt][1], ah[mt][2], ah[mt][3]);
                ldm4(ual + ao, al[mt][0], al[mt][1], al[mt][2], al[mt][3]);
            }
            #pragma unroll
            for (int np = 0; np < 4; np++) {
                unsigned bo = boff + np * 16 * PITCH + kb;
                unsigned bh[4], bl[4];
                ldm4(ubh + bo, bh[0], bh[1], bh[2], bh[3]);
                ldm4(ubl + bo, bl[0], bl[1], bl[2], bl[3]);
                #pragma unroll
                for (int mt = 0; mt < 2; mt++) {
                    hmma(acc[mt][2*np  ], ah[mt][0], ah[mt][1], ah[mt][2], ah[mt][3], bh[0], bh[1]);
                    hmma(acc[mt][2*np+1], ah[mt][0], ah[mt][1], ah[mt][2], ah[mt][3], bh[2], bh[3]);
                    hmma(acc[mt][2*np  ], ah[mt][0], ah[mt][1], ah[mt][2], ah[mt][3], bl[0], bl[1]);
                    hmma(acc[mt][2*np+1], ah[mt][0], ah[mt][1], ah[mt][2], ah[mt][3], bl[2], bl[3]);
                    hmma(acc[mt][2*np  ], al[mt][0], al[mt][1], al[mt][2], al[mt][3], bh[0], bh[1]);
                    hmma(acc[mt][2*np+1], al[mt][0], al[mt][1], al[mt][2], al[mt][3], bh[2], bh[3]);
                }
            }
        }
        __syncthreads();
    }

    const int qr = lane >> 2;
    const int qc = (lane & 3) << 1;
    #pragma unroll
    for (int mt = 0; mt < 2; mt++) {
        #pragma unroll
        for (int nt = 0; nt < 8; nt++) {
            int col = bn + wn * 64 + nt * 8 + qc;
            float2 bb = make_float2(0.f, 0.f);
            if (EPI != EPI_NONE) bb = *(const float2*)&bias[col];
            #pragma unroll
            for (int half = 0; half < 2; half++) {
                int row = bm + wm * 32 + mt * 16 + qr + half * 8;
                float2 v;
                v.x = half ? acc[mt][nt].z : acc[mt][nt].x;
                v.y = half ? acc[mt][nt].w : acc[mt][nt].y;
                if (EPI != EPI_NONE) { v.x += bb.x; v.y += bb.y; }
                if (EPI == EPI_BIAS_GELU) { v.x = gelu_tanh(v.x); v.y = gelu_tanh(v.y); }
                if (EPI == EPI_BIAS_RES) {
                    float2 rr = *(const float2*)&res[(size_t)row * ldres + col];
                    v.x += rr.x; v.y += rr.y;
                }
                if (OBF == 1) {
                    *(unsigned*)(Ch + (size_t)row * ldc + col) = pack2(v.x * scale, v.y * scale);
                } else if (OBF == 2) {
                    unsigned h, l; cvt2(v.x, v.y, h, l);
                    *(unsigned*)(Ch + (size_t)row * ldc + col) = h;
                    *(unsigned*)(Cl + (size_t)row * ldc + col) = l;
                } else {
                    *(float2*)&C[(size_t)row * ldc + col] = v;
                }
            }
        }
    }
}

// ================= fused flash attention (single-bf16 QKVP, cp.async KV) ====
#define FPITCH 144
#define QPL (128 * FPITCH)      // 18432
#define KVPL (64 * FPITCH)      // 9216
#define FLASH_SMEM (QPL + 4 * KVPL)   // 55296

__global__ __launch_bounds__(256, 2)
void flash_k()
{
    extern __shared__ char sm[];
    const unsigned uq  = sm2u(sm);
    const unsigned ukv = uq + QPL;     // 2 buffers x 2 planes (K, V)

    const int tid  = threadIdx.x;
    const int lane = tid & 31;
    const int wid  = tid >> 5;
    const int h    = blockIdx.y;
    const int bq   = blockIdx.x * 128;
    const int hc   = h * D_HEAD;

    auto issue = [&](int b, int kb) {
        const unsigned sb = ukv + b * (2 * KVPL);
        #pragma unroll
        for (int i = tid; i < 512; i += 256) {
            int r = i >> 3, cc = i & 7;
            unsigned so = r * FPITCH + cc * 16;
            size_t go = (size_t)(kb + r) * D_MODEL + hc + cc * 8;
            CPA16(sb + so,        g_kh + go);
            CPA16(sb + KVPL + so, g_vh + go);
        }
        CPA_COMMIT();
    };

    issue(0, 0);
    // Q tile copy (pre-scaled single bf16)
    for (int i = tid; i < 1024; i += 256) {
        int r = i >> 3, cc = i & 7;
        size_t go = (size_t)(bq + r) * D_MODEL + hc + cc * 8;
        *(uint4*)(sm + r * FPITCH + cc * 16) = *(const uint4*)(g_qh + go);
    }

    const unsigned aoff = (unsigned)(wid * 16 + (lane & 15)) * FPITCH + ((lane & 16) ? 16u : 0u);
    const unsigned boff = (unsigned)((lane & 7) + ((lane & 16) ? 8 : 0)) * FPITCH
                        + ((lane & 8) ? 16u : 0u);
    const unsigned voff = (unsigned)((lane & 7) + ((lane & 8) ? 8 : 0)) * FPITCH
                        + ((lane & 16) ? 16u : 0u);

    float4 oacc[8];
    #pragma unroll
    for (int t = 0; t < 8; t++) oacc[t] = make_float4(0.f, 0.f, 0.f, 0.f);
    float m0 = -1e30f, m1 = -1e30f, l0 = 0.f, l1 = 0.f;

    const int NITER = N_NODES / 64;
    for (int c = 0; c < NITER; c++) {
        const int b = c & 1;
        if (c + 1 < NITER) { issue(b ^ 1, (c + 1) * 64); CPA_WAIT1(); }
        else               { CPA_WAIT0(); }
        __syncthreads();

        const unsigned ukh = ukv + b * (2 * KVPL);
        const unsigned uvh = ukh + KVPL;

        // ---- S = Q K^T ----
        float4 sacc[8];
        #pragma unroll
        for (int t = 0; t < 8; t++) sacc[t] = make_float4(0.f, 0.f, 0.f, 0.f);
        #pragma unroll
        for (int t = 0; t < 4; t++) {
            unsigned ah[4];
            ldm4(uq + aoff + t * 32, ah[0], ah[1], ah[2], ah[3]);
            #pragma unroll
            for (int ng = 0; ng < 4; ng++) {
                unsigned bh[4];
                ldm4(ukh + boff + ng * (16 * FPITCH) + t * 32, bh[0], bh[1], bh[2], bh[3]);
                hmma(sacc[2*ng  ], ah[0], ah[1], ah[2], ah[3], bh[0], bh[1]);
                hmma(sacc[2*ng+1], ah[0], ah[1], ah[2], ah[3], bh[2], bh[3]);
            }
        }

        // ---- online softmax ----
        float mx0 = -1e30f, mx1 = -1e30f;
        #pragma unroll
        for (int t = 0; t < 8; t++) {
            mx0 = fmaxf(mx0, fmaxf(sacc[t].x, sacc[t].y));
            mx1 = fmaxf(mx1, fmaxf(sacc[t].z, sacc[t].w));
        }
        mx0 = fmaxf(mx0, __shfl_xor_sync(0xffffffffu, mx0, 1));
        mx0 = fmaxf(mx0, __shfl_xor_sync(0xffffffffu, mx0, 2));
        mx1 = fmaxf(mx1, __shfl_xor_sync(0xffffffffu, mx1, 1));
        mx1 = fmaxf(mx1, __shfl_xor_sync(0xffffffffu, mx1, 2));
        float mn0 = fmaxf(m0, mx0), mn1 = fmaxf(m1, mx1);
        float c0 = __expf(m0 - mn0), c1 = __expf(m1 - mn1);
        m0 = mn0; m1 = mn1;

        unsigned pxy[8], pzw[8];
        float s0 = 0.f, s1 = 0.f;
        #pragma unroll
        for (int t = 0; t < 8; t++) {
            float ex = __expf(sacc[t].x - mn0);
            float ey = __expf(sacc[t].y - mn0);
            float ez = __expf(sacc[t].z - mn1);
            float ew = __expf(sacc[t].w - mn1);
            s0 += ex + ey; s1 += ez + ew;
            pxy[t] = pack2(ex, ey);
            pzw[t] = pack2(ez, ew);
        }
        s0 += __shfl_xor_sync(0xffffffffu, s0, 1);
        s0 += __shfl_xor_sync(0xffffffffu, s0, 2);
        s1 += __shfl_xor_sync(0xffffffffu, s1, 1);
        s1 += __shfl_xor_sync(0xffffffffu, s1, 2);
        l0 = l0 * c0 + s0;
        l1 = l1 * c1 + s1;
        #pragma unroll
        for (int t = 0; t < 8; t++) {
            oacc[t].x *= c0; oacc[t].y *= c0;
            oacc[t].z *= c1; oacc[t].w *= c1;
        }

        // ---- O += P V ----
        #pragma unroll
        for (int t = 0; t < 4; t++) {
            unsigned a0 = pxy[2*t], a1 = pzw[2*t], a2 = pxy[2*t+1], a3 = pzw[2*t+1];
            #pragma unroll
            for (int ng = 0; ng < 4; ng++) {
                unsigned bh[4];
                ldm4t(uvh + voff + t * (16 * FPITCH) + ng * 32, bh[0], bh[1], bh[2], bh[3]);
                hmma(oacc[2*ng  ], a0, a1, a2, a3, bh[0], bh[1]);
                hmma(oacc[2*ng+1], a0, a1, a2, a3, bh[2], bh[3]);
            }
        }
        __syncthreads();
    }

    // ---- epilogue: write O as bf16 hi/lo (Wo GEMM needs split A) ----
    const int qr = lane >> 2;
    const int qc = (lane & 3) << 1;
    float inv0 = 1.0f / l0, inv1 = 1.0f / l1;
    int r0 = bq + wid * 16 + qr;
    int r1 = r0 + 8;
    #pragma unroll
    for (int t = 0; t < 8; t++) {
        int col = hc + t * 8 + qc;
        unsigned hh, ll;
        cvt2(oacc[t].x * inv0, oacc[t].y * inv0, hh, ll);
        *(unsigned*)(g_oh + (size_t)r0 * D_MODEL + col) = hh;
        *(unsigned*)(g_ol + (size_t)r0 * D_MODEL + col) = ll;
        cvt2(oacc[t].z * inv1, oacc[t].w * inv1, hh, ll);
        *(unsigned*)(g_oh + (size_t)r1 * D_MODEL + col) = hh;
        *(unsigned*)(g_ol + (size_t)r1 * D_MODEL + col) = ll;
    }
}

// ---------------- LayerNorm -> bf16 hi/lo ----------------
__global__ void ln_k(const float* __restrict__ x, const float* __restrict__ s,
                     const float* __restrict__ b, bf16* __restrict__ yh,
                     bf16* __restrict__ yl)
{
    const int row = blockIdx.x;
    const int tid = threadIdx.x;   // 256
    const float* xr = x + (size_t)row * D_MODEL;

    float2 xv = *(const float2*)&xr[2 * tid];
    float sum = xv.x + xv.y;
    float sq  = xv.x * xv.x + xv.y * xv.y;

#pragma unroll
    for (int off = 16; off > 0; off >>= 1) {
        sum += __shfl_xor_sync(0xffffffffu, sum, off);
        sq  += __shfl_xor_sync(0xffffffffu, sq,  off);
    }
    __shared__ float rs[8], rq[8];
    __shared__ float s_mean, s_inv;
    if ((tid & 31) == 0) { rs[tid >> 5] = sum; rq[tid >> 5] = sq; }
    __syncthreads();
    if (tid == 0) {
        float ts = 0.f, tq = 0.f;
#pragma unroll
        for (int i = 0; i < 8; i++) { ts += rs[i]; tq += rq[i]; }
        float mean = ts * (1.0f / D_MODEL);
        float var  = tq * (1.0f / D_MODEL) - mean * mean;
        s_mean = mean;
        s_inv  = rsqrtf(var + 1e-5f);
    }
    __syncthreads();
    float mean = s_mean, inv = s_inv;
    float2 sv = *(const float2*)&s[2 * tid];
    float2 bv = *(const float2*)&b[2 * tid];
    float v0 = (xv.x - mean) * inv * sv.x + bv.x;
    float v1 = (xv.y - mean) * inv * sv.y + bv.y;
    unsigned h, l; cvt2(v0, v1, h, l);
    *(unsigned*)(yh + (size_t)row * D_MODEL + 2 * tid) = h;
    *(unsigned*)(yl + (size_t)row * D_MODEL + 2 * tid) = l;
}

// ---------------- GCN kernels ----------------
__global__ void deg_acc_k(const int* __restrict__ ei, const float* __restrict__ ew) {
    int e = blockIdx.x * blockDim.x + threadIdx.x;
    if (e < N_EDGES) atomicAdd(&g_dinv[ei[N_EDGES + e]], ew[e]);
}
__global__ void deg_fin_k() {
    int i = blockIdx.x * blockDim.x + threadIdx.x;
    if (i < N_NODES) g_dinv[i] = rsqrtf(g_dinv[i]);
}
__global__ void mp_init_k(const float* __restrict__ bg) {
    int idx = blockIdx.x * blockDim.x + threadIdx.x;
    int n  = idx >> 7;
    int d4 = (idx & 127) << 2;
    float di = g_dinv[n];
    float c  = di * di;
    float4 xv = *(const float4*)&g_xt[(size_t)n * D_MODEL + d4];
    float4 bb = *(const float4*)&bg[d4];
    float4 r;
    r.x = fmaf(xv.x, c, bb.x); r.y = fmaf(xv.y, c, bb.y);
    r.z = fmaf(xv.z, c, bb.z); r.w = fmaf(xv.w, c, bb.w);
    *(float4*)&g_mp[(size_t)n * D_MODEL + d4] = r;
}
__global__ void scatter_k(const int* __restrict__ ei, const float* __restrict__ ew) {
    int idx = blockIdx.x * blockDim.x + threadIdx.x;
    int e  = idx >> 7;
    int d4 = (idx & 127) << 2;
    int s  = ei[e];
    int t  = ei[N_EDGES + e];
    float coef = g_dinv[s] * ew[e] * g_dinv[t];
    float4 xv = *(const float4*)&g_xt[(size_t)s * D_MODEL + d4];
    float* dstp = &g_mp[(size_t)t * D_MODEL + d4];
    atomicAdd(dstp + 0, xv.x * coef);
    atomicAdd(dstp + 1, xv.y * coef);
    atomicAdd(dstp + 2, xv.z * coef);
    atomicAdd(dstp + 3, xv.w * coef);
}

// ---------------- concat [mp | tf] -> cat bf16 hi/lo [N, 1024] ----------------
__global__ void concat_k() {
    int idx = blockIdx.x * blockDim.x + threadIdx.x;
    int n  = idx >> 7;
    int d4 = (idx & 127) << 2;
    float4 a = *(const float4*)&g_mp[(size_t)n * D_MODEL + d4];
    float4 b = *(const float4*)&g_tf[(size_t)n * D_MODEL + d4];
    uint2 h, l;
    cvt4(a.x, a.y, a.z, a.w, h, l);
    *(uint2*)(g_cth + (size_t)n * 1024 + d4) = h;
    *(uint2*)(g_ctl + (size_t)n * 1024 + d4) = l;
    cvt4(b.x, b.y, b.z, b.w, h, l);
    *(uint2*)(g_cth + (size_t)n * 1024 + 512 + d4) = h;
    *(uint2*)(g_ctl + (size_t)n * 1024 + 512 + d4) = l;
}

// ---------------- launch ----------------
extern "C" void kernel_launch(void* const* d_in, const int* in_sizes, int n_in,
                              void* d_out, int out_size)
{
    (void)in_sizes; (void)n_in; (void)out_size;
    const float* x     = (const float*)d_in[0];
    const int*   ei    = (const int*)  d_in[1];
    const float* ew    = (const float*)d_in[2];
    const float* Wg    = (const float*)d_in[3];
    const float* bg    = (const float*)d_in[4];
    const float* ln1_s = (const float*)d_in[5];
    const float* ln1_b = (const float*)d_in[6];
    const float* Wq    = (const float*)d_in[7];
    const float* bq    = (const float*)d_in[8];
    const float* Wk    = (const float*)d_in[9];
    const float* bk    = (const float*)d_in[10];
    const float* Wv    = (const float*)d_in[11];
    const float* bv    = (const float*)d_in[12];
    const float* Wo    = (const float*)d_in[13];
    const float* bo    = (const float*)d_in[14];
    const float* ln2_s = (const float*)d_in[15];
    const float* ln2_b = (const float*)d_in[16];
    const float* W1    = (const float*)d_in[17];
    const float* b1    = (const float*)d_in[18];
    const float* W2    = (const float*)d_in[19];
    const float* b2    = (const float*)d_in[20];
    const float* Wa    = (const float*)d_in[21];
    const float* ba    = (const float*)d_in[22];
    float* out = (float*)d_out;

    float *xt, *x1, *tf;
    cudaGetSymbolAddress((void**)&xt, g_xt);
    cudaGetSymbolAddress((void**)&x1, g_x1);
    cudaGetSymbolAddress((void**)&tf, g_tf);

#define SYM(p, g) bf16* p; cudaGetSymbolAddress((void**)&p, g)
    SYM(xbh, g_xbh); SYM(xbl, g_xbl);
    SYM(hh,  g_hh);  SYM(hl,  g_hl);
    SYM(qh,  g_qh);
    SYM(kh,  g_kh);
    SYM(vh,  g_vh);
    SYM(oh,  g_oh);  SYM(ol,  g_ol);
    SYM(h2h, g_h2h); SYM(h2l, g_h2l);
    SYM(m1h, g_m1h); SYM(m1l, g_m1l);
    SYM(cth, g_cth); SYM(ctl, g_ctl);
    SYM(Wgh, g_Wgh); SYM(Wgl, g_Wgl);
    SYM(Wqh, g_Wqh); SYM(Wql, g_Wql);
    SYM(Wkh, g_Wkh); SYM(Wkl, g_Wkl);
    SYM(Wvh, g_Wvh); SYM(Wvl, g_Wvl);
    SYM(Woh, g_Woh); SYM(Wol, g_Wol);
    SYM(W1h, g_W1h); SYM(W1l, g_W1l);
    SYM(W2h, g_W2h); SYM(W2l, g_W2l);
    SYM(Wah, g_Wah); SYM(Wal, g_Wal);
#undef SYM

    const int GSMEM = 2 * 4 * (128 * PITCH);   // 81920
    cudaFuncSetAttribute(tgemm2_k<EPI_NONE,      0>, cudaFuncAttributeMaxDynamicSharedMemorySize, GSMEM);
    cudaFuncSetAttribute(tgemm2_k<EPI_BIAS,      1>, cudaFuncAttributeMaxDynamicSharedMemorySize, GSMEM);
    cudaFuncSetAttribute(tgemm2_k<EPI_BIAS_GELU, 2>, cudaFuncAttributeMaxDynamicSharedMemorySize, GSMEM);
    cudaFuncSetAttribute(tgemm2_k<EPI_BIAS_RES,  0>, cudaFuncAttributeMaxDynamicSharedMemorySize, GSMEM);
    cudaFuncSetAttribute(flash_k, cudaFuncAttributeMaxDynamicSharedMemorySize, FLASH_SMEM);

    // ---- fused weight prep (one launch) ----
    WArgs wa;
    wa.s[0] = { Wg, Wgh, Wgl, D_MODEL, D_MODEL };
    wa.s[1] = { Wq, Wqh, Wql, D_MODEL, D_MODEL };
    wa.s[2] = { Wk, Wkh, Wkl, D_MODEL, D_MODEL };
    wa.s[3] = { Wv, Wvh, Wvl, D_MODEL, D_MODEL };
    wa.s[4] = { Wo, Woh, Wol, D_MODEL, D_MODEL };
    wa.s[5] = { W1, W1h, W1l, D_MODEL, D_FF };
    wa.s[6] = { W2, W2h, W2l, D_FF, D_MODEL };
    wa.s[7] = { Wa, Wah, Wal, 2 * D_MODEL, D_MODEL };
    wprep8_k<<<dim3(64, 64, 8), dim3(32, 8)>>>(wa);
    aprep_k<<<(N_NODES * D_MODEL / 4) / 256, 256>>>(x, xbh, xbl);

    dim3 g512(4, 32), gff(16, 32);

    // ---- GCN branch ----
    tgemm2_k<EPI_NONE, 0><<<g512, 256, GSMEM>>>(
        xbh, xbl, D_MODEL, Wgh, Wgl, xt, nullptr, nullptr, D_MODEL,
        nullptr, nullptr, 0, D_MODEL, 1.0f);
    deg_acc_k<<<N_EDGES / 256, 256>>>(ei, ew);
    deg_fin_k<<<N_NODES / 256, 256>>>();
    mp_init_k<<<(N_NODES * D_MODEL / 4) / 256, 256>>>(bg);
    scatter_k<<<(N_EDGES * (D_MODEL / 4)) / 256, 256>>>(ei, ew);

    // ---- Transformer branch ----
    ln_k<<<N_NODES, 256>>>(x, ln1_s, ln1_b, hh, hl);
    tgemm2_k<EPI_BIAS, 1><<<g512, 256, GSMEM>>>(
        hh, hl, D_MODEL, Wqh, Wql, nullptr, qh, nullptr, D_MODEL,
        bq, nullptr, 0, D_MODEL, 0.125f);
    tgemm2_k<EPI_BIAS, 1><<<g512, 256, GSMEM>>>(
        hh, hl, D_MODEL, Wkh, Wkl, nullptr, kh, nullptr, D_MODEL,
        bk, nullptr, 0, D_MODEL, 1.0f);
    tgemm2_k<EPI_BIAS, 1><<<g512, 256, GSMEM>>>(
        hh, hl, D_MODEL, Wvh, Wvl, nullptr, vh, nullptr, D_MODEL,
        bv, nullptr, 0, D_MODEL, 1.0f);

    flash_k<<<dim3(N_NODES / 128, N_HEADS), 256, FLASH_SMEM>>>();

    tgemm2_k<EPI_BIAS_RES, 0><<<g512, 256, GSMEM>>>(
        oh, ol, D_MODEL, Woh, Wol, x1, nullptr, nullptr, D_MODEL,
        bo, x, D_MODEL, D_MODEL, 1.0f);
    ln_k<<<N_NODES, 256>>>(x1, ln2_s, ln2_b, h2h, h2l);
    tgemm2_k<EPI_BIAS_GELU, 2><<<gff, 256, GSMEM>>>(
        h2h, h2l, D_MODEL, W1h, W1l, nullptr, m1h, m1l, D_FF,
        b1, nullptr, 0, D_MODEL, 1.0f);
    tgemm2_k<EPI_BIAS_RES, 0><<<g512, 256, GSMEM>>>(
        m1h, m1l, D_FF, W2h, W2l, tf, nullptr, nullptr, D_MODEL,
        b2, x1, D_MODEL, D_FF, 1.0f);

    // ---- merge ----
    concat_k<<<(N_NODES * D_MODEL / 4) / 256, 256>>>();
    tgemm2_k<EPI_BIAS_RES, 0><<<g512, 256, GSMEM>>>(
        cth, ctl, 2 * D_MODEL, Wah, Wal, out, nullptr, nullptr, D_MODEL,
        ba, x, D_MODEL, 2 * D_MODEL, 1.0f);
}

// round 13
// speedup vs baseline: 7.2350x; 1.1820x over previous
#include <cuda_runtime.h>
#include <cuda_bf16.h>
#include <math.h>

#define N_NODES 4096
#define D_MODEL 512
#define N_HEADS 8
#define D_HEAD  64
#define D_FF    2048
#define N_EDGES 65536

#define EPI_NONE      0
#define EPI_BIAS      1
#define EPI_BIAS_GELU 2
#define EPI_BIAS_RES  3

#define PITCH 80   // GEMM smem pitch: 32 bf16 (64B) + 16B pad
typedef __nv_bfloat16 bf16;

// ---------------- fp32 scratch ----------------
__device__ float g_xt [N_NODES * D_MODEL];
__device__ float g_mp [N_NODES * D_MODEL];
__device__ float g_deg [N_NODES];
__device__ float g_dinv[N_NODES];
__device__ float g_x1 [N_NODES * D_MODEL];
__device__ float g_tf [N_NODES * D_MODEL];

// ---------------- bf16 activations ----------------
__device__ bf16 g_xbh[N_NODES * D_MODEL],  g_xbl[N_NODES * D_MODEL];
__device__ bf16 g_hh [N_NODES * D_MODEL];
__device__ bf16 g_qh [N_NODES * D_MODEL];
__device__ bf16 g_kh [N_NODES * D_MODEL];
__device__ bf16 g_vh [N_NODES * D_MODEL];
__device__ bf16 g_oh [N_NODES * D_MODEL];
__device__ bf16 g_h2h[N_NODES * D_MODEL],  g_h2l[N_NODES * D_MODEL];
__device__ bf16 g_m1h[N_NODES * D_FF],     g_m1l[N_NODES * D_FF];
__device__ bf16 g_cth[N_NODES * 2*D_MODEL],g_ctl[N_NODES * 2*D_MODEL];

// ---------------- bf16 hi/lo transposed weights [N,K] ----------------
__device__ bf16 g_Wgh[D_MODEL*D_MODEL],  g_Wgl[D_MODEL*D_MODEL];
__device__ bf16 g_Wqh[D_MODEL*D_MODEL],  g_Wql[D_MODEL*D_MODEL];
__device__ bf16 g_Wkh[D_MODEL*D_MODEL],  g_Wkl[D_MODEL*D_MODEL];
__device__ bf16 g_Wvh[D_MODEL*D_MODEL],  g_Wvl[D_MODEL*D_MODEL];
__device__ bf16 g_Woh[D_MODEL*D_MODEL],  g_Wol[D_MODEL*D_MODEL];
__device__ bf16 g_W1h[D_MODEL*D_FF],     g_W1l[D_MODEL*D_FF];
__device__ bf16 g_W2h[D_FF*D_MODEL],     g_W2l[D_FF*D_MODEL];
__device__ bf16 g_Wah[2*D_MODEL*D_MODEL],g_Wal[2*D_MODEL*D_MODEL];

// ---------------- helpers ----------------
__device__ __forceinline__ float gelu_tanh(float x) {
    float x3 = x * x * x;
    float t  = tanhf(0.7978845608028654f * (x + 0.044715f * x3));
    return 0.5f * x * (1.0f + t);
}
__device__ __forceinline__ unsigned sm2u(const void* p) {
    unsigned a;
    asm("{ .reg .u64 t; cvta.to.shared.u64 t, %1; cvt.u32.u64 %0, t; }" : "=r"(a) : "l"(p));
    return a;
}
__device__ __forceinline__ void ldm4(unsigned addr, unsigned& r0, unsigned& r1,
                                     unsigned& r2, unsigned& r3) {
    asm volatile("ldmatrix.sync.aligned.m8n8.x4.shared.b16 {%0,%1,%2,%3}, [%4];"
                 : "=r"(r0), "=r"(r1), "=r"(r2), "=r"(r3) : "r"(addr));
}
__device__ __forceinline__ void ldm4t(unsigned addr, unsigned& r0, unsigned& r1,
                                      unsigned& r2, unsigned& r3) {
    asm volatile("ldmatrix.sync.aligned.m8n8.x4.trans.shared.b16 {%0,%1,%2,%3}, [%4];"
                 : "=r"(r0), "=r"(r1), "=r"(r2), "=r"(r3) : "r"(addr));
}
__device__ __forceinline__ void hmma(float4& d, unsigned a0, unsigned a1,
                                     unsigned a2, unsigned a3,
                                     unsigned b0, unsigned b1) {
    asm volatile("mma.sync.aligned.m16n8k16.row.col.f32.bf16.bf16.f32 "
                 "{%0,%1,%2,%3}, {%4,%5,%6,%7}, {%8,%9}, {%0,%1,%2,%3};"
                 : "+f"(d.x), "+f"(d.y), "+f"(d.z), "+f"(d.w)
                 : "r"(a0), "r"(a1), "r"(a2), "r"(a3), "r"(b0), "r"(b1));
}
__device__ __forceinline__ void cvt4(float x0, float x1, float x2, float x3,
                                     uint2& hi, uint2& lo) {
    bf16 h0 = __float2bfloat16(x0), h1 = __float2bfloat16(x1);
    bf16 h2 = __float2bfloat16(x2), h3 = __float2bfloat16(x3);
    bf16 l0 = __float2bfloat16(x0 - __bfloat162float(h0));
    bf16 l1 = __float2bfloat16(x1 - __bfloat162float(h1));
    bf16 l2 = __float2bfloat16(x2 - __bfloat162float(h2));
    bf16 l3 = __float2bfloat16(x3 - __bfloat162float(h3));
    hi.x = ((unsigned)__bfloat16_as_ushort(h1) << 16) | __bfloat16_as_ushort(h0);
    hi.y = ((unsigned)__bfloat16_as_ushort(h3) << 16) | __bfloat16_as_ushort(h2);
    lo.x = ((unsigned)__bfloat16_as_ushort(l1) << 16) | __bfloat16_as_ushort(l0);
    lo.y = ((unsigned)__bfloat16_as_ushort(l3) << 16) | __bfloat16_as_ushort(l2);
}
__device__ __forceinline__ void cvt2(float x, float y, unsigned& hi, unsigned& lo) {
    bf16 hx = __float2bfloat16(x), hy = __float2bfloat16(y);
    bf16 lx = __float2bfloat16(x - __bfloat162float(hx));
    bf16 ly = __float2bfloat16(y - __bfloat162float(hy));
    hi = ((unsigned)__bfloat16_as_ushort(hy) << 16) | __bfloat16_as_ushort(hx);
    lo = ((unsigned)__bfloat16_as_ushort(ly) << 16) | __bfloat16_as_ushort(lx);
}
__device__ __forceinline__ unsigned pack2(float x, float y) {
    unsigned r;
    asm("cvt.rn.bf16x2.f32 %0, %1, %2;" : "=r"(r) : "f"(y), "f"(x));
    return r;
}

#define CPA16(s, g)  asm volatile("cp.async.cg.shared.global [%0], [%1], 16;" :: "r"(s), "l"(g))
#define CPA_COMMIT() asm volatile("cp.async.commit_group;" ::: "memory")
#define CPA_WAIT1()  asm volatile("cp.async.wait_group 1;" ::: "memory")
#define CPA_WAIT0()  asm volatile("cp.async.wait_group 0;" ::: "memory")

// ================= prep kernels =================
struct WSeg { const float* W; bf16* hi; bf16* lo; int K; int N; };
struct WArgs { WSeg s[8]; };

__global__ void wprep8_k(WArgs a)
{
    __shared__ float t[32][33];
    WSeg p = a.s[blockIdx.z];
    int k0 = blockIdx.y * 32, n0 = blockIdx.x * 32;
    if (k0 >= p.K || n0 >= p.N) return;
    int tx = threadIdx.x, ty = threadIdx.y;   // 32 x 8
    #pragma unroll
    for (int i = 0; i < 4; i++)
        t[ty + 8*i][tx] = p.W[(size_t)(k0 + ty + 8*i) * p.N + n0 + tx];
    __syncthreads();
    #pragma unroll
    for (int i = 0; i < 4; i++) {
        float v = t[tx][ty + 8*i];
        bf16 h = __float2bfloat16(v);
        bf16 l = __float2bfloat16(v - __bfloat162float(h));
        size_t o = (size_t)(n0 + ty + 8*i) * p.K + k0 + tx;
        p.hi[o] = h; p.lo[o] = l;
    }
}
// fp32 -> bf16 hi/lo elementwise; also initializes deg (self-loop weight 1)
__global__ void aprep_k(const float* __restrict__ x, bf16* __restrict__ hi,
                        bf16* __restrict__ lo)
{
    int idx = blockIdx.x * blockDim.x + threadIdx.x;
    if (idx < N_NODES) g_deg[idx] = 1.0f;
    float4 v = *(const float4*)(x + idx * 4);
    uint2 h, l; cvt4(v.x, v.y, v.z, v.w, h, l);
    *(uint2*)(hi + idx * 4) = h;
    *(uint2*)(lo + idx * 4) = l;
}

// ================= cp.async double-buffered HMMA GEMM =================
// OBF: 0 = fp32 out, 1 = bf16 hi only, 2 = bf16 hi+lo
// SPLIT: true = 3-term hi/lo split MMA; false = single-bf16 (hi planes only)
template<int EPI, int OBF, bool SPLIT>
__global__ __launch_bounds__(256)
void tgemm2_k(const bf16* __restrict__ Ah, const bf16* __restrict__ Al, int lda,
              const bf16* __restrict__ Bh, const bf16* __restrict__ Bl,
              float* __restrict__ C, bf16* __restrict__ Ch, bf16* __restrict__ Cl,
              int ldc, const float* __restrict__ bias,
              const float* __restrict__ res, int ldres, int K, float scale)
{
    extern __shared__ char smem[];
    const int tid  = threadIdx.x;
    const int lane = tid & 31;
    const int wid  = tid >> 5;
    const int wm   = wid & 3;
    const int wn   = wid >> 2;
    const int bm   = blockIdx.y * 128;
    const int bn   = blockIdx.x * 128;

    constexpr int APL    = 128 * PITCH;        // 10240 bytes per plane
    constexpr int PLANES = SPLIT ? 4 : 2;
    const unsigned us = sm2u(smem);

    const bf16* g0 = Ah + (size_t)bm * lda;
    const bf16* g1 = SPLIT ? Al + (size_t)bm * lda : nullptr;
    const bf16* g2 = Bh + (size_t)bn * K;
    const bf16* g3 = SPLIT ? Bl + (size_t)bn * K : nullptr;

    auto issue = [&](int b, int c) {
        const int k0 = c * 32;
        const unsigned sb = us + b * (PLANES * APL);
        #pragma unroll
        for (int i = tid; i < 512; i += 256) {
            int r = i >> 2, cc = i & 3;
            unsigned so = r * PITCH + cc * 16;
            size_t goA = (size_t)r * lda + k0 + cc * 8;
            size_t goB = (size_t)r * K   + k0 + cc * 8;
            if (SPLIT) {
                CPA16(sb + 0*APL + so, g0 + goA);
                CPA16(sb + 1*APL + so, g1 + goA);
                CPA16(sb + 2*APL + so, g2 + goB);
                CPA16(sb + 3*APL + so, g3 + goB);
            } else {
                CPA16(sb + 0*APL + so, g0 + goA);
                CPA16(sb + 1*APL + so, g2 + goB);
            }
        }
        CPA_COMMIT();
    };

    float4 acc[2][8];
    #pragma unroll
    for (int i = 0; i < 2; i++)
        #pragma unroll
        for (int j = 0; j < 8; j++) acc[i][j] = make_float4(0.f, 0.f, 0.f, 0.f);

    const unsigned aoff = (unsigned)(wm * 32 + (lane & 15)) * PITCH + ((lane & 16) ? 16u : 0u);
    const unsigned boff = (unsigned)(wn * 64 + (lane & 7) + ((lane & 16) ? 8 : 0)) * PITCH
                        + ((lane & 8) ? 16u : 0u);

    const int nch = K >> 5;
    issue(0, 0);
    for (int c = 0; c < nch; c++) {
        const int b = c & 1;
        if (c + 1 < nch) { issue(b ^ 1, c + 1); CPA_WAIT1(); }
        else             { CPA_WAIT0(); }
        __syncthreads();

        const unsigned uah = us + b * (PLANES * APL);
        const unsigned ual = uah + APL;                       // only if SPLIT
        const unsigned ubh = uah + (SPLIT ? 2 : 1) * APL;
        const unsigned ubl = uah + 3 * APL;                   // only if SPLIT

        #pragma unroll
        for (int ks = 0; ks < 2; ks++) {
            const unsigned kb = ks * 32;
            unsigned ah[2][4], al[2][4];
            #pragma unroll
            for (int mt = 0; mt < 2; mt++) {
                unsigned ao = aoff + mt * 16 * PITCH + kb;
                ldm4(uah + ao, ah[mt][0], ah[mt][1], ah[mt][2], ah[mt][3]);
                if (SPLIT)
                    ldm4(ual + ao, al[mt][0], al[mt][1], al[mt][2], al[mt][3]);
            }
            #pragma unroll
            for (int np = 0; np < 4; np++) {
                unsigned bo = boff + np * 16 * PITCH + kb;
                unsigned bh[4], bl[4];
                ldm4(ubh + bo, bh[0], bh[1], bh[2], bh[3]);
                if (SPLIT)
                    ldm4(ubl + bo, bl[0], bl[1], bl[2], bl[3]);
                #pragma unroll
                for (int mt = 0; mt < 2; mt++) {
                    hmma(acc[mt][2*np  ], ah[mt][0], ah[mt][1], ah[mt][2], ah[mt][3], bh[0], bh[1]);
                    hmma(acc[mt][2*np+1], ah[mt][0], ah[mt][1], ah[mt][2], ah[mt][3], bh[2], bh[3]);
                    if (SPLIT) {
                        hmma(acc[mt][2*np  ], ah[mt][0], ah[mt][1], ah[mt][2], ah[mt][3], bl[0], bl[1]);
                        hmma(acc[mt][2*np+1], ah[mt][0], ah[mt][1], ah[mt][2], ah[mt][3], bl[2], bl[3]);
                        hmma(acc[mt][2*np  ], al[mt][0], al[mt][1], al[mt][2], al[mt][3], bh[0], bh[1]);
                        hmma(acc[mt][2*np+1], al[mt][0], al[mt][1], al[mt][2], al[mt][3], bh[2], bh[3]);
                    }
                }
            }
        }
        __syncthreads();
    }

    const int qr = lane >> 2;
    const int qc = (lane & 3) << 1;
    #pragma unroll
    for (int mt = 0; mt < 2; mt++) {
        #pragma unroll
        for (int nt = 0; nt < 8; nt++) {
            int col = bn + wn * 64 + nt * 8 + qc;
            float2 bb = make_float2(0.f, 0.f);
            if (EPI != EPI_NONE) bb = *(const float2*)&bias[col];
            #pragma unroll
            for (int half = 0; half < 2; half++) {
                int row = bm + wm * 32 + mt * 16 + qr + half * 8;
                float2 v;
                v.x = half ? acc[mt][nt].z : acc[mt][nt].x;
                v.y = half ? acc[mt][nt].w : acc[mt][nt].y;
                if (EPI != EPI_NONE) { v.x += bb.x; v.y += bb.y; }
                if (EPI == EPI_BIAS_GELU) { v.x = gelu_tanh(v.x); v.y = gelu_tanh(v.y); }
                if (EPI == EPI_BIAS_RES) {
                    float2 rr = *(const float2*)&res[(size_t)row * ldres + col];
                    v.x += rr.x; v.y += rr.y;
                }
                if (OBF == 1) {
                    *(unsigned*)(Ch + (size_t)row * ldc + col) = pack2(v.x * scale, v.y * scale);
                } else if (OBF == 2) {
                    unsigned h, l; cvt2(v.x, v.y, h, l);
                    *(unsigned*)(Ch + (size_t)row * ldc + col) = h;
                    *(unsigned*)(Cl + (size_t)row * ldc + col) = l;
                } else {
                    *(float2*)&C[(size_t)row * ldc + col] = v;
                }
            }
        }
    }
}

// ================= fused flash attention (single-bf16 QKVP, cp.async KV) ====
#define FPITCH 144
#define QPL (128 * FPITCH)      // 18432
#define KVPL (64 * FPITCH)      // 9216
#define FLASH_SMEM (QPL + 4 * KVPL)   // 55296

__global__ __launch_bounds__(256, 2)
void flash_k()
{
    extern __shared__ char sm[];
    const unsigned uq  = sm2u(sm);
    const unsigned ukv = uq + QPL;     // 2 buffers x 2 planes (K, V)

    const int tid  = threadIdx.x;
    const int lane = tid & 31;
    const int wid  = tid >> 5;
    const int h    = blockIdx.y;
    const int bq   = blockIdx.x * 128;
    const int hc   = h * D_HEAD;

    auto issue = [&](int b, int kb) {
        const unsigned sb = ukv + b * (2 * KVPL);
        #pragma unroll
        for (int i = tid; i < 512; i += 256) {
            int r = i >> 3, cc = i & 7;
            unsigned so = r * FPITCH + cc * 16;
            size_t go = (size_t)(kb + r) * D_MODEL + hc + cc * 8;
            CPA16(sb + so,        g_kh + go);
            CPA16(sb + KVPL + so, g_vh + go);
        }
        CPA_COMMIT();
    };

    issue(0, 0);
    for (int i = tid; i < 1024; i += 256) {
        int r = i >> 3, cc = i & 7;
        size_t go = (size_t)(bq + r) * D_MODEL + hc + cc * 8;
        *(uint4*)(sm + r * FPITCH + cc * 16) = *(const uint4*)(g_qh + go);
    }

    const unsigned aoff = (unsigned)(wid * 16 + (lane & 15)) * FPITCH + ((lane & 16) ? 16u : 0u);
    const unsigned boff = (unsigned)((lane & 7) + ((lane & 16) ? 8 : 0)) * FPITCH
                        + ((lane & 8) ? 16u : 0u);
    const unsigned voff = (unsigned)((lane & 7) + ((lane & 8) ? 8 : 0)) * FPITCH
                        + ((lane & 16) ? 16u : 0u);

    float4 oacc[8];
    #pragma unroll
    for (int t = 0; t < 8; t++) oacc[t] = make_float4(0.f, 0.f, 0.f, 0.f);
    float m0 = -1e30f, m1 = -1e30f, l0 = 0.f, l1 = 0.f;

    const int NITER = N_NODES / 64;
    for (int c = 0; c < NITER; c++) {
        const int b = c & 1;
        if (c + 1 < NITER) { issue(b ^ 1, (c + 1) * 64); CPA_WAIT1(); }
        else               { CPA_WAIT0(); }
        __syncthreads();

        const unsigned ukh = ukv + b * (2 * KVPL);
        const unsigned uvh = ukh + KVPL;

        float4 sacc[8];
        #pragma unroll
        for (int t = 0; t < 8; t++) sacc[t] = make_float4(0.f, 0.f, 0.f, 0.f);
        #pragma unroll
        for (int t = 0; t < 4; t++) {
            unsigned ah[4];
            ldm4(uq + aoff + t * 32, ah[0], ah[1], ah[2], ah[3]);
            #pragma unroll
            for (int ng = 0; ng < 4; ng++) {
                unsigned bh[4];
                ldm4(ukh + boff + ng * (16 * FPITCH) + t * 32, bh[0], bh[1], bh[2], bh[3]);
                hmma(sacc[2*ng  ], ah[0], ah[1], ah[2], ah[3], bh[0], bh[1]);
                hmma(sacc[2*ng+1], ah[0], ah[1], ah[2], ah[3], bh[2], bh[3]);
            }
        }

        float mx0 = -1e30f, mx1 = -1e30f;
        #pragma unroll
        for (int t = 0; t < 8; t++) {
            mx0 = fmaxf(mx0, fmaxf(sacc[t].x, sacc[t].y));
            mx1 = fmaxf(mx1, fmaxf(sacc[t].z, sacc[t].w));
        }
        mx0 = fmaxf(mx0, __shfl_xor_sync(0xffffffffu, mx0, 1));
        mx0 = fmaxf(mx0, __shfl_xor_sync(0xffffffffu, mx0, 2));
        mx1 = fmaxf(mx1, __shfl_xor_sync(0xffffffffu, mx1, 1));
        mx1 = fmaxf(mx1, __shfl_xor_sync(0xffffffffu, mx1, 2));
        float mn0 = fmaxf(m0, mx0), mn1 = fmaxf(m1, mx1);
        float c0 = __expf(m0 - mn0), c1 = __expf(m1 - mn1);
        m0 = mn0; m1 = mn1;

        unsigned pxy[8], pzw[8];
        float s0 = 0.f, s1 = 0.f;
        #pragma unroll
        for (int t = 0; t < 8; t++) {
            float ex = __expf(sacc[t].x - mn0);
            float ey = __expf(sacc[t].y - mn0);
            float ez = __expf(sacc[t].z - mn1);
            float ew = __expf(sacc[t].w - mn1);
            s0 += ex + ey; s1 += ez + ew;
            pxy[t] = pack2(ex, ey);
            pzw[t] = pack2(ez, ew);
        }
        s0 += __shfl_xor_sync(0xffffffffu, s0, 1);
        s0 += __shfl_xor_sync(0xffffffffu, s0, 2);
        s1 += __shfl_xor_sync(0xffffffffu, s1, 1);
        s1 += __shfl_xor_sync(0xffffffffu, s1, 2);
        l0 = l0 * c0 + s0;
        l1 = l1 * c1 + s1;
        #pragma unroll
        for (int t = 0; t < 8; t++) {
            oacc[t].x *= c0; oacc[t].y *= c0;
            oacc[t].z *= c1; oacc[t].w *= c1;
        }

        #pragma unroll
        for (int t = 0; t < 4; t++) {
            unsigned a0 = pxy[2*t], a1 = pzw[2*t], a2 = pxy[2*t+1], a3 = pzw[2*t+1];
            #pragma unroll
            for (int ng = 0; ng < 4; ng++) {
                unsigned bh[4];
                ldm4t(uvh + voff + t * (16 * FPITCH) + ng * 32, bh[0], bh[1], bh[2], bh[3]);
                hmma(oacc[2*ng  ], a0, a1, a2, a3, bh[0], bh[1]);
                hmma(oacc[2*ng+1], a0, a1, a2, a3, bh[2], bh[3]);
            }
        }
        __syncthreads();
    }

    // ---- epilogue: O hi-plane only (Wo GEMM is single-bf16) ----
    const int qr = lane >> 2;
    const int qc = (lane & 3) << 1;
    float inv0 = 1.0f / l0, inv1 = 1.0f / l1;
    int r0 = bq + wid * 16 + qr;
    int r1 = r0 + 8;
    #pragma unroll
    for (int t = 0; t < 8; t++) {
        int col = hc + t * 8 + qc;
        *(unsigned*)(g_oh + (size_t)r0 * D_MODEL + col) =
            pack2(oacc[t].x * inv0, oacc[t].y * inv0);
        *(unsigned*)(g_oh + (size_t)r1 * D_MODEL + col) =
            pack2(oacc[t].z * inv1, oacc[t].w * inv1);
    }
}

// ---------------- LayerNorm -> bf16 (hi always, lo optional) ----------------
__global__ void ln_k(const float* __restrict__ x, const float* __restrict__ s,
                     const float* __restrict__ b, bf16* __restrict__ yh,
                     bf16* __restrict__ yl)
{
    const int row = blockIdx.x;
    const int tid = threadIdx.x;   // 256
    const float* xr = x + (size_t)row * D_MODEL;

    float2 xv = *(const float2*)&xr[2 * tid];
    float sum = xv.x + xv.y;
    float sq  = xv.x * xv.x + xv.y * xv.y;

#pragma unroll
    for (int off = 16; off > 0; off >>= 1) {
        sum += __shfl_xor_sync(0xffffffffu, sum, off);
        sq  += __shfl_xor_sync(0xffffffffu, sq,  off);
    }
    __shared__ float rs[8], rq[8];
    __shared__ float s_mean, s_inv;
    if ((tid & 31) == 0) { rs[tid >> 5] = sum; rq[tid >> 5] = sq; }
    __syncthreads();
    if (tid == 0) {
        float ts = 0.f, tq = 0.f;
#pragma unroll
        for (int i = 0; i < 8; i++) { ts += rs[i]; tq += rq[i]; }
        float mean = ts * (1.0f / D_MODEL);
        float var  = tq * (1.0f / D_MODEL) - mean * mean;
        s_mean = mean;
        s_inv  = rsqrtf(var + 1e-5f);
    }
    __syncthreads();
    float mean = s_mean, inv = s_inv;
    float2 sv = *(const float2*)&s[2 * tid];
    float2 bv = *(const float2*)&b[2 * tid];
    float v0 = (xv.x - mean) * inv * sv.x + bv.x;
    float v1 = (xv.y - mean) * inv * sv.y + bv.y;
    if (yl) {
        unsigned h, l; cvt2(v0, v1, h, l);
        *(unsigned*)(yh + (size_t)row * D_MODEL + 2 * tid) = h;
        *(unsigned*)(yl + (size_t)row * D_MODEL + 2 * tid) = l;
    } else {
        *(unsigned*)(yh + (size_t)row * D_MODEL + 2 * tid) = pack2(v0, v1);
    }
}

// ---------------- GCN kernels ----------------
__global__ void deg_acc_k(const int* __restrict__ ei, const float* __restrict__ ew) {
    int e = blockIdx.x * blockDim.x + threadIdx.x;
    if (e < N_EDGES) atomicAdd(&g_deg[ei[N_EDGES + e]], ew[e]);
}
// mp init + deg finalize (raw degree in g_deg; dinv written once per row)
__global__ void mp_init_k(const float* __restrict__ bg) {
    int idx = blockIdx.x * blockDim.x + threadIdx.x;
    int n  = idx >> 7;
    int d4 = (idx & 127) << 2;
    float deg = g_deg[n];
    float di  = rsqrtf(deg);
    float c   = di * di;
    float4 xv = *(const float4*)&g_xt[(size_t)n * D_MODEL + d4];
    float4 bb = *(const float4*)&bg[d4];
    float4 r;
    r.x = fmaf(xv.x, c, bb.x); r.y = fmaf(xv.y, c, bb.y);
    r.z = fmaf(xv.z, c, bb.z); r.w = fmaf(xv.w, c, bb.w);
    *(float4*)&g_mp[(size_t)n * D_MODEL + d4] = r;
    if (d4 == 0) g_dinv[n] = di;
}
__global__ void scatter_k(const int* __restrict__ ei, const float* __restrict__ ew) {
    int idx = blockIdx.x * blockDim.x + threadIdx.x;
    int e  = idx >> 7;
    int d4 = (idx & 127) << 2;
    int s  = ei[e];
    int t  = ei[N_EDGES + e];
    float coef = g_dinv[s] * ew[e] * g_dinv[t];
    float4 xv = *(const float4*)&g_xt[(size_t)s * D_MODEL + d4];
    float* dstp = &g_mp[(size_t)t * D_MODEL + d4];
    asm volatile("red.global.add.v4.f32 [%0], {%1,%2,%3,%4};"
                 :: "l"(dstp), "f"(xv.x * coef), "f"(xv.y * coef),
                    "f"(xv.z * coef), "f"(xv.w * coef) : "memory");
}

// ---------------- concat [mp | tf] -> cat bf16 hi/lo [N, 1024] ----------------
__global__ void concat_k() {
    int idx = blockIdx.x * blockDim.x + threadIdx.x;
    int n  = idx >> 7;
    int d4 = (idx & 127) << 2;
    float4 a = *(const float4*)&g_mp[(size_t)n * D_MODEL + d4];
    float4 b = *(const float4*)&g_tf[(size_t)n * D_MODEL + d4];
    uint2 h, l;
    cvt4(a.x, a.y, a.z, a.w, h, l);
    *(uint2*)(g_cth + (size_t)n * 1024 + d4) = h;
    *(uint2*)(g_ctl + (size_t)n * 1024 + d4) = l;
    cvt4(b.x, b.y, b.z, b.w, h, l);
    *(uint2*)(g_cth + (size_t)n * 1024 + 512 + d4) = h;
    *(uint2*)(g_ctl + (size_t)n * 1024 + 512 + d4) = l;
}

// ---------------- launch ----------------
extern "C" void kernel_launch(void* const* d_in, const int* in_sizes, int n_in,
                              void* d_out, int out_size)
{
    (void)in_sizes; (void)n_in; (void)out_size;
    const float* x     = (const float*)d_in[0];
    const int*   ei    = (const int*)  d_in[1];
    const float* ew    = (const float*)d_in[2];
    const float* Wg    = (const float*)d_in[3];
    const float* bg    = (const float*)d_in[4];
    const float* ln1_s = (const float*)d_in[5];
    const float* ln1_b = (const float*)d_in[6];
    const float* Wq    = (const float*)d_in[7];
    const float* bq    = (const float*)d_in[8];
    const float* Wk    = (const float*)d_in[9];
    const float* bk    = (const float*)d_in[10];
    const float* Wv    = (const float*)d_in[11];
    const float* bv    = (const float*)d_in[12];
    const float* Wo    = (const float*)d_in[13];
    const float* bo    = (const float*)d_in[14];
    const float* ln2_s = (const float*)d_in[15];
    const float* ln2_b = (const float*)d_in[16];
    const float* W1    = (const float*)d_in[17];
    const float* b1    = (const float*)d_in[18];
    const float* W2    = (const float*)d_in[19];
    const float* b2    = (const float*)d_in[20];
    const float* Wa    = (const float*)d_in[21];
    const float* ba    = (const float*)d_in[22];
    float* out = (float*)d_out;

    float *xt, *x1, *tf;
    cudaGetSymbolAddress((void**)&xt, g_xt);
    cudaGetSymbolAddress((void**)&x1, g_x1);
    cudaGetSymbolAddress((void**)&tf, g_tf);

#define SYM(p, g) bf16* p; cudaGetSymbolAddress((void**)&p, g)
    SYM(xbh, g_xbh); SYM(xbl, g_xbl);
    SYM(hh,  g_hh);
    SYM(qh,  g_qh);
    SYM(kh,  g_kh);
    SYM(vh,  g_vh);
    SYM(oh,  g_oh);
    SYM(h2h, g_h2h); SYM(h2l, g_h2l);
    SYM(m1h, g_m1h); SYM(m1l, g_m1l);
    SYM(cth, g_cth); SYM(ctl, g_ctl);
    SYM(Wgh, g_Wgh); SYM(Wgl, g_Wgl);
    SYM(Wqh, g_Wqh); SYM(Wql, g_Wql);
    SYM(Wkh, g_Wkh); SYM(Wkl, g_Wkl);
    SYM(Wvh, g_Wvh); SYM(Wvl, g_Wvl);
    SYM(Woh, g_Woh); SYM(Wol, g_Wol);
    SYM(W1h, g_W1h); SYM(W1l, g_W1l);
    SYM(W2h, g_W2h); SYM(W2l, g_W2l);
    SYM(Wah, g_Wah); SYM(Wal, g_Wal);
#undef SYM

    const int GSMEM4 = 2 * 4 * (128 * PITCH);   // 81920 (split)
    const int GSMEM2 = 2 * 2 * (128 * PITCH);   // 40960 (single)
    cudaFuncSetAttribute(tgemm2_k<EPI_NONE,      0, true >, cudaFuncAttributeMaxDynamicSharedMemorySize, GSMEM4);
    cudaFuncSetAttribute(tgemm2_k<EPI_BIAS_GELU, 2, true >, cudaFuncAttributeMaxDynamicSharedMemorySize, GSMEM4);
    cudaFuncSetAttribute(tgemm2_k<EPI_BIAS_RES,  0, true >, cudaFuncAttributeMaxDynamicSharedMemorySize, GSMEM4);
    cudaFuncSetAttribute(tgemm2_k<EPI_BIAS,      1, false>, cudaFuncAttributeMaxDynamicSharedMemorySize, GSMEM2);
    cudaFuncSetAttribute(tgemm2_k<EPI_BIAS_RES,  0, false>, cudaFuncAttributeMaxDynamicSharedMemorySize, GSMEM2);
    cudaFuncSetAttribute(flash_k, cudaFuncAttributeMaxDynamicSharedMemorySize, FLASH_SMEM);

    // ---- fused weight prep (one launch) ----
    WArgs wa;
    wa.s[0] = { Wg, Wgh, Wgl, D_MODEL, D_MODEL };
    wa.s[1] = { Wq, Wqh, Wql, D_MODEL, D_MODEL };
    wa.s[2] = { Wk, Wkh, Wkl, D_MODEL, D_MODEL };
    wa.s[3] = { Wv, Wvh, Wvl, D_MODEL, D_MODEL };
    wa.s[4] = { Wo, Woh, Wol, D_MODEL, D_MODEL };
    wa.s[5] = { W1, W1h, W1l, D_MODEL, D_FF };
    wa.s[6] = { W2, W2h, W2l, D_FF, D_MODEL };
    wa.s[7] = { Wa, Wah, Wal, 2 * D_MODEL, D_MODEL };
    wprep8_k<<<dim3(64, 64, 8), dim3(32, 8)>>>(wa);
    aprep_k<<<(N_NODES * D_MODEL / 4) / 256, 256>>>(x, xbh, xbl);

    dim3 g512(4, 32), gff(16, 32);

    // ---- GCN branch ----
    tgemm2_k<EPI_NONE, 0, true><<<g512, 256, GSMEM4>>>(
        xbh, xbl, D_MODEL, Wgh, Wgl, xt, nullptr, nullptr, D_MODEL,
        nullptr, nullptr, 0, D_MODEL, 1.0f);
    deg_acc_k<<<N_EDGES / 256, 256>>>(ei, ew);
    mp_init_k<<<(N_NODES * D_MODEL / 4) / 256, 256>>>(bg);
    scatter_k<<<(N_EDGES * (D_MODEL / 4)) / 256, 256>>>(ei, ew);

    // ---- Transformer branch ----
    ln_k<<<N_NODES, 256>>>(x, ln1_s, ln1_b, hh, nullptr);
    tgemm2_k<EPI_BIAS, 1, false><<<g512, 256, GSMEM2>>>(
        hh, nullptr, D_MODEL, Wqh, nullptr, nullptr, qh, nullptr, D_MODEL,
        bq, nullptr, 0, D_MODEL, 0.125f);
    tgemm2_k<EPI_BIAS, 1, false><<<g512, 256, GSMEM2>>>(
        hh, nullptr, D_MODEL, Wkh, nullptr, nullptr, kh, nullptr, D_MODEL,
        bk, nullptr, 0, D_MODEL, 1.0f);
    tgemm2_k<EPI_BIAS, 1, false><<<g512, 256, GSMEM2>>>(
        hh, nullptr, D_MODEL, Wvh, nullptr, nullptr, vh, nullptr, D_MODEL,
        bv, nullptr, 0, D_MODEL, 1.0f);

    flash_k<<<dim3(N_NODES / 128, N_HEADS), 256, FLASH_SMEM>>>();

    tgemm2_k<EPI_BIAS_RES, 0, false><<<g512, 256, GSMEM2>>>(
        oh, nullptr, D_MODEL, Woh, nullptr, x1, nullptr, nullptr, D_MODEL,
        bo, x, D_MODEL, D_MODEL, 1.0f);
    ln_k<<<N_NODES, 256>>>(x1, ln2_s, ln2_b, h2h, h2l);
    tgemm2_k<EPI_BIAS_GELU, 2, true><<<gff, 256, GSMEM4>>>(
        h2h, h2l, D_MODEL, W1h, W1l, nullptr, m1h, m1l, D_FF,
        b1, nullptr, 0, D_MODEL, 1.0f);
    tgemm2_k<EPI_BIAS_RES, 0, true><<<g512, 256, GSMEM4>>>(
        m1h, m1l, D_FF, W2h, W2l, tf, nullptr, nullptr, D_MODEL,
        b2, x1, D_MODEL, D_FF, 1.0f);

    // ---- merge ----
    concat_k<<<(N_NODES * D_MODEL / 4) / 256, 256>>>();
    tgemm2_k<EPI_BIAS_RES, 0, true><<<g512, 256, GSMEM4>>>(
        cth, ctl, 2 * D_MODEL, Wah, Wal, out, nullptr, nullptr, D_MODEL,
        ba, x, D_MODEL, 2 * D_MODEL, 1.0f);
}